// round 4
// baseline (speedup 1.0000x reference)
#include <cuda_runtime.h>

// ProcessorCNN: 3-step sphere GNN.
//   per step i:
//     S  = x @ Ws[i]            (GEMM)
//     Nn = x @ Wn[i]            (GEMM)
//     h  = x + S + bs[i] + (1/6)*sum_{t<6} Nn[nbr[t]] + bn[i]
//     x  = relu( LN(h) * ln_scale[i] + ln_offset[i] )
//
// Uses mean(x[nbr]) @ Wn == (1/6) * sum (x@Wn)[nbr]  -> gather AFTER projection.

#define NNODES 50000
#define LAT    256
#define KNB    6
#define LN_EPS 1e-5f

// Scratch (static device globals; no allocation in kernel_launch)
__device__ float g_x [NNODES * LAT];
__device__ float g_S [NNODES * LAT];
__device__ float g_Nn[NNODES * LAT];

#define BM 128
#define BN 128
#define BK 16

// C[z] = A[M,256] @ W[z][256,256];  z=0 -> g_S (Ws), z=1 -> g_Nn (Wn)
__global__ __launch_bounds__(256, 2)
void sgemm_dual(const float* __restrict__ A,
                const float* __restrict__ Ws,
                const float* __restrict__ Wn)
{
    const float* B = blockIdx.z ? Wn : Ws;
    float*       C = blockIdx.z ? g_Nn : g_S;

    __shared__ float As[2][BK][BM];   // transposed: As[k][m]
    __shared__ float Bs[2][BK][BN];   // natural:    Bs[k][n]

    const int tid = threadIdx.x;           // 256 threads
    const int m0  = blockIdx.y * BM;
    const int n0  = blockIdx.x * BN;

    // A-tile: 128 rows x 16 k = 512 float4; each thread loads 2 (rows t>>2 and t>>2+64)
    const int arow = tid >> 2;             // 0..63
    const int acol = (tid & 3) << 2;       // 0,4,8,12
    // B-tile: 16 k-rows x 128 cols = 512 float4; each thread loads 2 (k-rows t>>5 and t>>5+8)
    const int brow = tid >> 5;             // 0..7
    const int bcol = (tid & 31) << 2;      // 0..124

    // compute map: 16x16 threads, 8x8 micro-tile
    const int trow = (tid >> 4) << 3;
    const int tcol = (tid & 15) << 3;

    float acc[8][8];
#pragma unroll
    for (int i = 0; i < 8; i++)
#pragma unroll
        for (int j = 0; j < 8; j++) acc[i][j] = 0.0f;

    // ---- prologue: load k-slab 0 into buffer 0 ----
    {
        const int r0 = m0 + arow, r1 = m0 + arow + 64;
        float4 a0 = make_float4(0.f, 0.f, 0.f, 0.f);
        float4 a1 = make_float4(0.f, 0.f, 0.f, 0.f);
        if (r0 < NNODES) a0 = *reinterpret_cast<const float4*>(A + r0 * LAT + acol);
        if (r1 < NNODES) a1 = *reinterpret_cast<const float4*>(A + r1 * LAT + acol);
        As[0][acol + 0][arow] = a0.x;  As[0][acol + 1][arow] = a0.y;
        As[0][acol + 2][arow] = a0.z;  As[0][acol + 3][arow] = a0.w;
        As[0][acol + 0][arow + 64] = a1.x;  As[0][acol + 1][arow + 64] = a1.y;
        As[0][acol + 2][arow + 64] = a1.z;  As[0][acol + 3][arow + 64] = a1.w;
        float4 b0 = *reinterpret_cast<const float4*>(B + brow * LAT + n0 + bcol);
        float4 b1 = *reinterpret_cast<const float4*>(B + (brow + 8) * LAT + n0 + bcol);
        *reinterpret_cast<float4*>(&Bs[0][brow][bcol])     = b0;
        *reinterpret_cast<float4*>(&Bs[0][brow + 8][bcol]) = b1;
    }
    __syncthreads();

    int buf = 0;
    for (int k0 = 0; k0 < LAT; k0 += BK) {
        const int nxt = buf ^ 1;
        if (k0 + BK < LAT) {
            const int kb = k0 + BK;
            const int r0 = m0 + arow, r1 = m0 + arow + 64;
            float4 a0 = make_float4(0.f, 0.f, 0.f, 0.f);
            float4 a1 = make_float4(0.f, 0.f, 0.f, 0.f);
            if (r0 < NNODES) a0 = *reinterpret_cast<const float4*>(A + r0 * LAT + kb + acol);
            if (r1 < NNODES) a1 = *reinterpret_cast<const float4*>(A + r1 * LAT + kb + acol);
            As[nxt][acol + 0][arow] = a0.x;  As[nxt][acol + 1][arow] = a0.y;
            As[nxt][acol + 2][arow] = a0.z;  As[nxt][acol + 3][arow] = a0.w;
            As[nxt][acol + 0][arow + 64] = a1.x;  As[nxt][acol + 1][arow + 64] = a1.y;
            As[nxt][acol + 2][arow + 64] = a1.z;  As[nxt][acol + 3][arow + 64] = a1.w;
            float4 b0 = *reinterpret_cast<const float4*>(B + (kb + brow) * LAT + n0 + bcol);
            float4 b1 = *reinterpret_cast<const float4*>(B + (kb + brow + 8) * LAT + n0 + bcol);
            *reinterpret_cast<float4*>(&Bs[nxt][brow][bcol])     = b0;
            *reinterpret_cast<float4*>(&Bs[nxt][brow + 8][bcol]) = b1;
        }

#pragma unroll
        for (int kk = 0; kk < BK; kk++) {
            float af[8], bf[8];
            *reinterpret_cast<float4*>(&af[0]) =
                *reinterpret_cast<const float4*>(&As[buf][kk][trow]);
            *reinterpret_cast<float4*>(&af[4]) =
                *reinterpret_cast<const float4*>(&As[buf][kk][trow + 4]);
            *reinterpret_cast<float4*>(&bf[0]) =
                *reinterpret_cast<const float4*>(&Bs[buf][kk][tcol]);
            *reinterpret_cast<float4*>(&bf[4]) =
                *reinterpret_cast<const float4*>(&Bs[buf][kk][tcol + 4]);
#pragma unroll
            for (int i = 0; i < 8; i++)
#pragma unroll
                for (int j = 0; j < 8; j++)
                    acc[i][j] = fmaf(af[i], bf[j], acc[i][j]);
        }
        __syncthreads();
        buf = nxt;
    }

#pragma unroll
    for (int i = 0; i < 8; i++) {
        const int gr = m0 + trow + i;
        if (gr < NNODES) {
            float* cp = C + gr * LAT + n0 + tcol;
            *reinterpret_cast<float4*>(cp) =
                make_float4(acc[i][0], acc[i][1], acc[i][2], acc[i][3]);
            *reinterpret_cast<float4*>(cp + 4) =
                make_float4(acc[i][4], acc[i][5], acc[i][6], acc[i][7]);
        }
    }
}

// h = x + S + bs + bn + (1/6)*sum Nn[nbr];  out = relu(LN(h)*scale + offset)
// one block (64 threads) per row; each thread handles 4 contiguous floats
__global__ __launch_bounds__(64)
void combine_k(const float* __restrict__ x,
               const float* __restrict__ bsv,
               const float* __restrict__ bnv,
               const float* __restrict__ gam,
               const float* __restrict__ bet,
               const int*   __restrict__ nbr,
               float*       __restrict__ out)
{
    const int row = blockIdx.x;
    const int t   = threadIdx.x;     // 64
    const int j   = t << 2;
    const int base = row * LAT + j;

    const int* nb = nbr + row * KNB;
    const int n0 = nb[0], n1 = nb[1], n2 = nb[2], n3 = nb[3], n4 = nb[4], n5 = nb[5];

    const float4 xv = *reinterpret_cast<const float4*>(x + base);
    const float4 sv = *reinterpret_cast<const float4*>(g_S + base);

    float4 a = *reinterpret_cast<const float4*>(g_Nn + n0 * LAT + j);
    const float4 a1 = *reinterpret_cast<const float4*>(g_Nn + n1 * LAT + j);
    const float4 a2 = *reinterpret_cast<const float4*>(g_Nn + n2 * LAT + j);
    const float4 a3 = *reinterpret_cast<const float4*>(g_Nn + n3 * LAT + j);
    const float4 a4 = *reinterpret_cast<const float4*>(g_Nn + n4 * LAT + j);
    const float4 a5 = *reinterpret_cast<const float4*>(g_Nn + n5 * LAT + j);
    a.x += a1.x + a2.x + a3.x + a4.x + a5.x;
    a.y += a1.y + a2.y + a3.y + a4.y + a5.y;
    a.z += a1.z + a2.z + a3.z + a4.z + a5.z;
    a.w += a1.w + a2.w + a3.w + a4.w + a5.w;

    const float4 bq = *reinterpret_cast<const float4*>(bsv + j);
    const float4 nq = *reinterpret_cast<const float4*>(bnv + j);

    const float inv6 = 1.0f / 6.0f;
    float4 h;
    h.x = xv.x + sv.x + bq.x + nq.x + a.x * inv6;
    h.y = xv.y + sv.y + bq.y + nq.y + a.y * inv6;
    h.z = xv.z + sv.z + bq.z + nq.z + a.z * inv6;
    h.w = xv.w + sv.w + bq.w + nq.w + a.w * inv6;

    // row reduction for mean / var over 256 elements
    float s = h.x + h.y + h.z + h.w;
    float q = fmaf(h.x, h.x, fmaf(h.y, h.y, fmaf(h.z, h.z, h.w * h.w)));
#pragma unroll
    for (int o = 16; o > 0; o >>= 1) {
        s += __shfl_xor_sync(0xffffffffu, s, o);
        q += __shfl_xor_sync(0xffffffffu, q, o);
    }
    __shared__ float sh[4];
    if ((t & 31) == 0) { sh[(t >> 5) * 2] = s; sh[(t >> 5) * 2 + 1] = q; }
    __syncthreads();
    s = sh[0] + sh[2];
    q = sh[1] + sh[3];

    const float mu  = s * (1.0f / LAT);
    const float var = q * (1.0f / LAT) - mu * mu;
    const float inv = rsqrtf(var + LN_EPS);

    const float4 g = *reinterpret_cast<const float4*>(gam + j);
    const float4 b = *reinterpret_cast<const float4*>(bet + j);

    float4 o4;
    o4.x = fmaxf(0.0f, (h.x - mu) * inv * g.x + b.x);
    o4.y = fmaxf(0.0f, (h.y - mu) * inv * g.y + b.y);
    o4.z = fmaxf(0.0f, (h.z - mu) * inv * g.z + b.z);
    o4.w = fmaxf(0.0f, (h.w - mu) * inv * g.w + b.w);
    *reinterpret_cast<float4*>(out + base) = o4;
}

extern "C" void kernel_launch(void* const* d_in, const int* in_sizes, int n_in,
                              void* d_out, int out_size)
{
    const float* x0  = (const float*)d_in[0];   // sphere_nodes [50000,256]
    const float* Ws  = (const float*)d_in[1];   // [3,256,256]
    const float* bs  = (const float*)d_in[2];   // [3,256]
    const float* Wn  = (const float*)d_in[3];   // [3,256,256]
    const float* bn  = (const float*)d_in[4];   // [3,256]
    const float* lsc = (const float*)d_in[5];   // [3,256]
    const float* lof = (const float*)d_in[6];   // [3,256]
    const int*   nbr = (const int*)d_in[7];     // [50000,6]
    float* out = (float*)d_out;

    float* xbuf = nullptr;
    cudaGetSymbolAddress((void**)&xbuf, g_x);   // host-side query; capture-safe

    const dim3 gg(LAT / BN, (NNODES + BM - 1) / BM, 2);
    const dim3 gb(256);
    const dim3 cg(NNODES);
    const dim3 cb(64);
    const int  WW = LAT * LAT;

    // step 0: read external input, write xbuf
    sgemm_dual<<<gg, gb>>>(x0, Ws, Wn);
    combine_k<<<cg, cb>>>(x0, bs, bn, lsc, lof, nbr, xbuf);
    // step 1: in-place on xbuf (combine reads only its own row of x)
    sgemm_dual<<<gg, gb>>>(xbuf, Ws + WW, Wn + WW);
    combine_k<<<cg, cb>>>(xbuf, bs + LAT, bn + LAT, lsc + LAT, lof + LAT, nbr, xbuf);
    // step 2: write final output
    sgemm_dual<<<gg, gb>>>(xbuf, Ws + 2 * WW, Wn + 2 * WW);
    combine_k<<<cg, cb>>>(xbuf, bs + 2 * LAT, bn + 2 * LAT, lsc + 2 * LAT, lof + 2 * LAT, nbr, out);
}

// round 7
// speedup vs baseline: 2.4247x; 2.4247x over previous
#include <cuda_runtime.h>
#include <cuda_bf16.h>
#include <cstdint>

// ProcessorCNN: 3-step sphere GNN.  mma.sync (HMMA) bf16 hi/lo-split GEMM path.
// (tcgen05 is rejected by the harness's compute_103 PTX stage; mma.sync is the
//  portable tensor-core ISA and compiles fine.)
//   C = xhi*Whi + xlo*Whi + xhi*Wlo   (fp32 accum; drops ~2^-16 xlo*Wlo term)
//   treated as one K=768 GEMM: part 0: (xhi,Whi) 1: (xlo,Whi) 2: (xhi,Wlo)
// mean(x[nbr]) @ Wn == (1/6) * sum (x@Wn)[nbr]  -> gather AFTER projection.

#define NNODES 50000
#define LAT    256
#define KNB    6
#define LN_EPS 1e-5f

#define BM 128
#define BN 128
#define BKC 64           // k-chunk per pipeline stage
#define NKIT 12          // 768 / 64
#define NTILES 391       // ceil(50000/128)

// ---- device scratch ----
__device__ float         g_x  [NNODES * LAT];
__device__ float         g_S  [NNODES * LAT];
__device__ float         g_Nn [NNODES * LAT];
__device__ __nv_bfloat16 g_xhi[NNODES * LAT];
__device__ __nv_bfloat16 g_xlo[NNODES * LAT];
__device__ __nv_bfloat16 g_Whi[6 * LAT * LAT];   // [part][k][n]  (original layout)
__device__ __nv_bfloat16 g_Wlo[6 * LAT * LAT];

__device__ __forceinline__ uint32_t smem_u32(const void* p) {
    uint32_t a;
    asm("{ .reg .u64 t; cvta.to.shared.u64 t, %1; cvt.u32.u64 %0, t; }" : "=r"(a) : "l"(p));
    return a;
}
#define SWZ(o) ((o) ^ (((o) >> 3) & 0x70))
// B-tile swizzle: [k][n] rows of 256B (16 granules); rotate low-3 granule bits by k
#define BSWZ(k, gn) ((k) * 256 + ((((gn) & 8) | (((gn) ^ (k)) & 7)) << 4))

__device__ __forceinline__ void cpa16(uint32_t dst, const void* src, uint32_t n) {
    asm volatile("cp.async.cg.shared.global [%0], [%1], 16, %2;"
                 :: "r"(dst), "l"(src), "r"(n) : "memory");
}
#define CP_COMMIT() asm volatile("cp.async.commit_group;" ::: "memory")
#define CP_WAIT1()  asm volatile("cp.async.wait_group 1;" ::: "memory")

// smem: A stages at 0/16384 (128 rows x 64 k, 128B rows, SWZ), B at 32768/49152
// ([k][n]: 64 k-rows x 128 n, 256B rows, BSWZ).  total 64 KB.
#define GEMM_SMEM 65536

// ============================================================================
// GEMM: C[z] = x @ W[z]  (z=0 -> g_S w/ Ws, z=1 -> g_Nn w/ Wn)
// ============================================================================
__global__ __launch_bounds__(256, 2)
void gemm_mma(const __nv_bfloat16* __restrict__ xh,
              const __nv_bfloat16* __restrict__ xl,
              int wbase)
{
    extern __shared__ char smem[];
    const uint32_t sb = smem_u32(smem);
    const int tid = threadIdx.x, lane = tid & 31, wid = tid >> 5;
    const int wm = wid >> 2, wn = wid & 3;          // 2 x 4 warp grid (64x32 tiles)
    const int m0 = blockIdx.y * BM;
    const int n0 = blockIdx.x * BN;
    const __nv_bfloat16* Wh = g_Whi + (wbase + blockIdx.z) * (LAT * LAT);
    const __nv_bfloat16* Wl = g_Wlo + (wbase + blockIdx.z) * (LAT * LAT);
    float* C = blockIdx.z ? g_Nn : g_S;

    float acc[4][4][4];
#pragma unroll
    for (int a = 0; a < 4; a++)
#pragma unroll
        for (int b = 0; b < 4; b++)
#pragma unroll
            for (int c = 0; c < 4; c++) acc[a][b][c] = 0.0f;

    // ---- stage loader: part = kk/4 selects (A,B) operand pair, kc = (kk%4)*64
#define LOAD_STAGE(kk, buf) do {                                                  \
        const int _part = (kk) >> 2, _kc = ((kk) & 3) * BKC;                      \
        const __nv_bfloat16* _Ap = (_part == 1) ? xl : xh;                        \
        const __nv_bfloat16* _Bp = (_part == 2) ? Wl : Wh;                        \
        const uint32_t _aB = sb + (buf) * 16384;                                  \
        const uint32_t _bB = sb + 32768 + (buf) * 16384;                          \
        _Pragma("unroll")                                                         \
        for (int _i = 0; _i < 4; _i++) {                                          \
            const int _idx = tid + _i * 256;                                      \
            const int _r = _idx >> 3, _g = _idx & 7;                              \
            const int _grow = m0 + _r;                                            \
            const int _srow = (_grow < NNODES) ? _grow : 0;                       \
            cpa16(_aB + SWZ(_r * 128 + _g * 16),                                  \
                  _Ap + _srow * LAT + _kc + _g * 8,                               \
                  (_grow < NNODES) ? 16u : 0u);                                   \
        }                                                                         \
        _Pragma("unroll")                                                         \
        for (int _i = 0; _i < 4; _i++) {                                          \
            const int _idx = tid + _i * 256;                                      \
            const int _k = _idx >> 4, _gn = _idx & 15;                            \
            cpa16(_bB + BSWZ(_k, _gn),                                            \
                  _Bp + (_kc + _k) * LAT + n0 + _gn * 8, 16u);                    \
        }                                                                         \
        CP_COMMIT();                                                              \
    } while (0)

    LOAD_STAGE(0, 0);

    for (int kk = 0; kk < NKIT; kk++) {
        const int buf = kk & 1;
        if (kk + 1 < NKIT) LOAD_STAGE(kk + 1, buf ^ 1);
        else               CP_COMMIT();              // keep group count uniform
        CP_WAIT1();
        __syncthreads();

        const uint32_t aB = sb + buf * 16384;
        const uint32_t bB = sb + 32768 + buf * 16384;
#pragma unroll
        for (int k16 = 0; k16 < 4; k16++) {
            uint32_t af[4][4], bf[4][2];
#pragma unroll
            for (int mi = 0; mi < 4; mi++) {
                const int row = wm * 64 + mi * 16 + (lane & 15);
                const uint32_t ad = aB + SWZ(row * 128 + k16 * 32 + (lane >> 4) * 16);
                asm volatile("ldmatrix.sync.aligned.m8n8.x4.shared.b16 {%0,%1,%2,%3}, [%4];"
                    : "=r"(af[mi][0]), "=r"(af[mi][1]), "=r"(af[mi][2]), "=r"(af[mi][3])
                    : "r"(ad));
            }
#pragma unroll
            for (int ni = 0; ni < 4; ni++) {
                const int kl = k16 * 16 + (lane & 15);
                const int gn = wn * 4 + ni;
                const uint32_t bd = bB + BSWZ(kl, gn);
                asm volatile("ldmatrix.sync.aligned.m8n8.x2.trans.shared.b16 {%0,%1}, [%2];"
                    : "=r"(bf[ni][0]), "=r"(bf[ni][1]) : "r"(bd));
            }
#pragma unroll
            for (int mi = 0; mi < 4; mi++)
#pragma unroll
                for (int ni = 0; ni < 4; ni++)
                    asm volatile(
                        "mma.sync.aligned.m16n8k16.row.col.f32.bf16.bf16.f32 "
                        "{%0,%1,%2,%3}, {%4,%5,%6,%7}, {%8,%9}, {%0,%1,%2,%3};"
                        : "+f"(acc[mi][ni][0]), "+f"(acc[mi][ni][1]),
                          "+f"(acc[mi][ni][2]), "+f"(acc[mi][ni][3])
                        : "r"(af[mi][0]), "r"(af[mi][1]), "r"(af[mi][2]), "r"(af[mi][3]),
                          "r"(bf[ni][0]), "r"(bf[ni][1]));
        }
        __syncthreads();
    }
#undef LOAD_STAGE

    // epilogue: fp32 stores (c0,c1)=(row, col..col+1), (c2,c3)=row+8
#pragma unroll
    for (int mi = 0; mi < 4; mi++) {
        const int r0 = m0 + wm * 64 + mi * 16 + (lane >> 2);
#pragma unroll
        for (int ni = 0; ni < 4; ni++) {
            const int c = n0 + wn * 32 + ni * 8 + (lane & 3) * 2;
            if (r0 < NNODES)
                *reinterpret_cast<float2*>(C + r0 * LAT + c) =
                    make_float2(acc[mi][ni][0], acc[mi][ni][1]);
            if (r0 + 8 < NNODES)
                *reinterpret_cast<float2*>(C + (r0 + 8) * LAT + c) =
                    make_float2(acc[mi][ni][2], acc[mi][ni][3]);
        }
    }
}

// ============================================================================
// prep: elementwise bf16 hi/lo split of the 6 weight matrices (layout kept [k][n])
// ============================================================================
__global__ __launch_bounds__(256)
void prep_w(const float* __restrict__ Ws, const float* __restrict__ Wn)
{
    const int idx = blockIdx.x * 256 + threadIdx.x;     // < 6*65536
    const int p = idx >> 16, rem = idx & 65535;
    const float* src = (p & 1) ? Wn : Ws;
    const float v = src[(p >> 1) * 65536 + rem];
    const __nv_bfloat16 h = __float2bfloat16(v);
    g_Whi[idx] = h;
    g_Wlo[idx] = __float2bfloat16(v - __bfloat162float(h));
}

// convert fp32 x -> bf16 hi/lo (step-0 input)
__global__ __launch_bounds__(256)
void cvt_x(const float* __restrict__ x)
{
    const int i = (blockIdx.x * 256 + threadIdx.x) * 4;
    const float4 v = *reinterpret_cast<const float4*>(x + i);
    __nv_bfloat16 h0 = __float2bfloat16(v.x), h1 = __float2bfloat16(v.y);
    __nv_bfloat16 h2 = __float2bfloat16(v.z), h3 = __float2bfloat16(v.w);
    __nv_bfloat162 hi0 = {h0, h1}, hi1 = {h2, h3};
    __nv_bfloat162 lo0 = {__float2bfloat16(v.x - __bfloat162float(h0)),
                          __float2bfloat16(v.y - __bfloat162float(h1))};
    __nv_bfloat162 lo1 = {__float2bfloat16(v.z - __bfloat162float(h2)),
                          __float2bfloat16(v.w - __bfloat162float(h3))};
    *reinterpret_cast<__nv_bfloat162*>(g_xhi + i)     = hi0;
    *reinterpret_cast<__nv_bfloat162*>(g_xhi + i + 2) = hi1;
    *reinterpret_cast<__nv_bfloat162*>(g_xlo + i)     = lo0;
    *reinterpret_cast<__nv_bfloat162*>(g_xlo + i + 2) = lo1;
}

// ============================================================================
// combine: h = x + S + bs + bn + (1/6)*sum Nn[nbr]; out = relu(LN(h)*g+b)
// also emits bf16 hi/lo of out for the next step's GEMM (when oxh != null)
// ============================================================================
__global__ __launch_bounds__(64)
void combine_k(const float* __restrict__ x,
               const float* __restrict__ bsv,
               const float* __restrict__ bnv,
               const float* __restrict__ gam,
               const float* __restrict__ bet,
               const int*   __restrict__ nbr,
               float*       __restrict__ out,
               __nv_bfloat16* __restrict__ oxh,
               __nv_bfloat16* __restrict__ oxl)
{
    const int row = blockIdx.x;
    const int t   = threadIdx.x;
    const int j   = t << 2;
    const int base = row * LAT + j;

    const int* nb = nbr + row * KNB;
    const int n0 = nb[0], n1 = nb[1], n2 = nb[2], n3 = nb[3], n4 = nb[4], n5 = nb[5];

    const float4 xv = *reinterpret_cast<const float4*>(x + base);
    const float4 sv = *reinterpret_cast<const float4*>(g_S + base);

    float4 a = *reinterpret_cast<const float4*>(g_Nn + n0 * LAT + j);
    const float4 a1 = *reinterpret_cast<const float4*>(g_Nn + n1 * LAT + j);
    const float4 a2 = *reinterpret_cast<const float4*>(g_Nn + n2 * LAT + j);
    const float4 a3 = *reinterpret_cast<const float4*>(g_Nn + n3 * LAT + j);
    const float4 a4 = *reinterpret_cast<const float4*>(g_Nn + n4 * LAT + j);
    const float4 a5 = *reinterpret_cast<const float4*>(g_Nn + n5 * LAT + j);
    a.x += a1.x + a2.x + a3.x + a4.x + a5.x;
    a.y += a1.y + a2.y + a3.y + a4.y + a5.y;
    a.z += a1.z + a2.z + a3.z + a4.z + a5.z;
    a.w += a1.w + a2.w + a3.w + a4.w + a5.w;

    const float4 bq = *reinterpret_cast<const float4*>(bsv + j);
    const float4 nq = *reinterpret_cast<const float4*>(bnv + j);

    const float inv6 = 1.0f / 6.0f;
    float4 h;
    h.x = xv.x + sv.x + bq.x + nq.x + a.x * inv6;
    h.y = xv.y + sv.y + bq.y + nq.y + a.y * inv6;
    h.z = xv.z + sv.z + bq.z + nq.z + a.z * inv6;
    h.w = xv.w + sv.w + bq.w + nq.w + a.w * inv6;

    float s = h.x + h.y + h.z + h.w;
    float q = fmaf(h.x, h.x, fmaf(h.y, h.y, fmaf(h.z, h.z, h.w * h.w)));
#pragma unroll
    for (int o = 16; o > 0; o >>= 1) {
        s += __shfl_xor_sync(0xffffffffu, s, o);
        q += __shfl_xor_sync(0xffffffffu, q, o);
    }
    __shared__ float sh[4];
    if ((t & 31) == 0) { sh[(t >> 5) * 2] = s; sh[(t >> 5) * 2 + 1] = q; }
    __syncthreads();
    s = sh[0] + sh[2];
    q = sh[1] + sh[3];

    const float mu  = s * (1.0f / LAT);
    const float var = q * (1.0f / LAT) - mu * mu;
    const float inv = rsqrtf(var + LN_EPS);

    const float4 g = *reinterpret_cast<const float4*>(gam + j);
    const float4 b = *reinterpret_cast<const float4*>(bet + j);

    float4 o4;
    o4.x = fmaxf(0.0f, (h.x - mu) * inv * g.x + b.x);
    o4.y = fmaxf(0.0f, (h.y - mu) * inv * g.y + b.y);
    o4.z = fmaxf(0.0f, (h.z - mu) * inv * g.z + b.z);
    o4.w = fmaxf(0.0f, (h.w - mu) * inv * g.w + b.w);
    *reinterpret_cast<float4*>(out + base) = o4;

    if (oxh) {
        __nv_bfloat16 h0 = __float2bfloat16(o4.x), h1 = __float2bfloat16(o4.y);
        __nv_bfloat16 h2 = __float2bfloat16(o4.z), h3 = __float2bfloat16(o4.w);
        __nv_bfloat162 hv0 = {h0, h1}, hv1 = {h2, h3};
        __nv_bfloat162 lv0 = {__float2bfloat16(o4.x - __bfloat162float(h0)),
                              __float2bfloat16(o4.y - __bfloat162float(h1))};
        __nv_bfloat162 lv1 = {__float2bfloat16(o4.z - __bfloat162float(h2)),
                              __float2bfloat16(o4.w - __bfloat162float(h3))};
        *reinterpret_cast<__nv_bfloat162*>(oxh + base)     = hv0;
        *reinterpret_cast<__nv_bfloat162*>(oxh + base + 2) = hv1;
        *reinterpret_cast<__nv_bfloat162*>(oxl + base)     = lv0;
        *reinterpret_cast<__nv_bfloat162*>(oxl + base + 2) = lv1;
    }
}

extern "C" void kernel_launch(void* const* d_in, const int* in_sizes, int n_in,
                              void* d_out, int out_size)
{
    const float* x0  = (const float*)d_in[0];
    const float* Ws  = (const float*)d_in[1];
    const float* bs  = (const float*)d_in[2];
    const float* Wn  = (const float*)d_in[3];
    const float* bn  = (const float*)d_in[4];
    const float* lsc = (const float*)d_in[5];
    const float* lof = (const float*)d_in[6];
    const int*   nbr = (const int*)d_in[7];
    float* out = (float*)d_out;

    float* xbuf = nullptr;
    __nv_bfloat16 *xhi = nullptr, *xlo = nullptr;
    cudaGetSymbolAddress((void**)&xbuf, g_x);
    cudaGetSymbolAddress((void**)&xhi,  g_xhi);
    cudaGetSymbolAddress((void**)&xlo,  g_xlo);

    cudaFuncSetAttribute(gemm_mma, cudaFuncAttributeMaxDynamicSharedMemorySize, GEMM_SMEM);

    const dim3 gg(LAT / BN, NTILES, 2);   // (2, 391, 2)
    const dim3 gb(256);
    const dim3 cg(NNODES);
    const dim3 cb(64);

    prep_w<<<6 * 65536 / 256, 256>>>(Ws, Wn);
    cvt_x<<<NNODES * LAT / 1024, 256>>>(x0);

    // step 0
    gemm_mma<<<gg, gb, GEMM_SMEM>>>(xhi, xlo, 0);
    combine_k<<<cg, cb>>>(x0, bs, bn, lsc, lof, nbr, xbuf, xhi, xlo);
    // step 1
    gemm_mma<<<gg, gb, GEMM_SMEM>>>(xhi, xlo, 2);
    combine_k<<<cg, cb>>>(xbuf, bs + LAT, bn + LAT, lsc + LAT, lof + LAT, nbr, xbuf, xhi, xlo);
    // step 2 (final -> d_out)
    gemm_mma<<<gg, gb, GEMM_SMEM>>>(xhi, xlo, 4);
    combine_k<<<cg, cb>>>(xbuf, bs + 2 * LAT, bn + 2 * LAT, lsc + 2 * LAT, lof + 2 * LAT,
                          nbr, out, (__nv_bfloat16*)nullptr, (__nv_bfloat16*)nullptr);
}

// round 9
// speedup vs baseline: 2.4570x; 1.0133x over previous
#include <cuda_runtime.h>
#include <cuda_bf16.h>
#include <cstdint>

// ProcessorCNN: 3-step sphere GNN.  mma.sync (HMMA) bf16 hi/lo-split GEMM path.
//   C = xhi*Whi + xhi*Wlo + xlo*Whi   (fp32 accum; drops ~2^-18 xlo*Wlo term)
//   Stage order interleaves parts so A tiles are reused on adjacent stages:
//     s=0..7 : (chunk s>>1) x (s odd ? Wlo : Whi)  with A=xhi loaded at even s
//     s=8..11: (chunk s&3)  x Whi                  with A=xlo loaded every s
//   A buffers and B buffers have independent parities (A_BUF below).
// mean(x[nbr]) @ Wn == (1/6) * sum (x@Wn)[nbr]  -> gather AFTER projection.

#define NNODES 50000
#define LAT    256
#define KNB    6
#define LN_EPS 1e-5f

#define BM 128
#define BN 128
#define BKC 64           // k-chunk per pipeline stage
#define NKIT 12          // 12 stages total
#define NTILES 391       // ceil(50000/128)

// ---- device scratch ----
__device__ float         g_x  [NNODES * LAT];
__device__ float         g_S  [NNODES * LAT];
__device__ float         g_Nn [NNODES * LAT];
__device__ __nv_bfloat16 g_xhi[NNODES * LAT];
__device__ __nv_bfloat16 g_xlo[NNODES * LAT];
__device__ __nv_bfloat16 g_Whi[6 * LAT * LAT];   // [part][k][n]  (original layout)
__device__ __nv_bfloat16 g_Wlo[6 * LAT * LAT];

__device__ __forceinline__ uint32_t smem_u32(const void* p) {
    uint32_t a;
    asm("{ .reg .u64 t; cvta.to.shared.u64 t, %1; cvt.u32.u64 %0, t; }" : "=r"(a) : "l"(p));
    return a;
}
#define SWZ(o) ((o) ^ (((o) >> 3) & 0x70))
// B-tile swizzle: [k][n] rows of 256B (16 granules); rotate low-3 granule bits by k
#define BSWZ(k, gn) ((k) * 256 + ((((gn) & 8) | (((gn) ^ (k)) & 7)) << 4))

__device__ __forceinline__ void cpa16(uint32_t dst, const void* src, uint32_t n) {
    asm volatile("cp.async.cg.shared.global [%0], [%1], 16, %2;"
                 :: "r"(dst), "l"(src), "r"(n) : "memory");
}
#define CP_COMMIT() asm volatile("cp.async.commit_group;" ::: "memory")
#define CP_WAIT1()  asm volatile("cp.async.wait_group 1;" ::: "memory")

// smem: A stages at 0/16384 (128 rows x 64 k, 128B rows, SWZ), B at 32768/49152
// ([k][n]: 64 k-rows x 128 n, 256B rows, BSWZ).  total 64 KB.
#define GEMM_SMEM 65536

// A-buffer parity decoupled from stage parity (reuse on odd s<8)
#define A_BUF(s) (((s) < 8) ? (((s) >> 1) & 1) : ((s) & 1))

// ============================================================================
// GEMM: C[z] = x @ W[z]  (z=0 -> g_S w/ Ws, z=1 -> g_Nn w/ Wn)
// ============================================================================
__global__ __launch_bounds__(256, 2)
void gemm_mma(const __nv_bfloat16* __restrict__ xh,
              const __nv_bfloat16* __restrict__ xl,
              int wbase)
{
    extern __shared__ char smem[];
    const uint32_t sb = smem_u32(smem);
    const int tid = threadIdx.x, lane = tid & 31, wid = tid >> 5;
    const int wm = wid >> 2, wn = wid & 3;          // 2 x 4 warp grid (64x32 tiles)
    const int m0 = blockIdx.y * BM;
    const int n0 = blockIdx.x * BN;
    const __nv_bfloat16* Wh = g_Whi + (wbase + blockIdx.z) * (LAT * LAT);
    const __nv_bfloat16* Wl = g_Wlo + (wbase + blockIdx.z) * (LAT * LAT);
    float* C = blockIdx.z ? g_Nn : g_S;

    float acc[4][4][4];
#pragma unroll
    for (int a = 0; a < 4; a++)
#pragma unroll
        for (int b = 0; b < 4; b++)
#pragma unroll
            for (int c = 0; c < 4; c++) acc[a][b][c] = 0.0f;

    // ---- stage loader (see header comment for the stage schedule) ----
#define LOAD_STAGE(s) do {                                                        \
        const int  _s  = (s);                                                     \
        const int  _ck = (_s < 8) ? (_s >> 1) : (_s & 3);                         \
        const int  _kc = _ck * BKC;                                               \
        const bool _doA = (_s < 8) ? ((_s & 1) == 0) : true;                      \
        const __nv_bfloat16* _Ap = (_s < 8) ? xh : xl;                            \
        const __nv_bfloat16* _Bp = ((_s < 8) && (_s & 1)) ? Wl : Wh;              \
        const uint32_t _aB = sb + A_BUF(_s) * 16384;                              \
        const uint32_t _bB = sb + 32768 + (_s & 1) * 16384;                       \
        if (_doA) {                                                               \
            _Pragma("unroll")                                                     \
            for (int _i = 0; _i < 4; _i++) {                                      \
                const int _idx = tid + _i * 256;                                  \
                const int _r = _idx >> 3, _g = _idx & 7;                          \
                const int _grow = m0 + _r;                                        \
                const int _srow = (_grow < NNODES) ? _grow : 0;                   \
                cpa16(_aB + SWZ(_r * 128 + _g * 16),                              \
                      _Ap + _srow * LAT + _kc + _g * 8,                           \
                      (_grow < NNODES) ? 16u : 0u);                               \
            }                                                                     \
        }                                                                         \
        _Pragma("unroll")                                                         \
        for (int _i = 0; _i < 4; _i++) {                                          \
            const int _idx = tid + _i * 256;                                      \
            const int _k = _idx >> 4, _gn = _idx & 15;                            \
            cpa16(_bB + BSWZ(_k, _gn),                                            \
                  _Bp + (_kc + _k) * LAT + n0 + _gn * 8, 16u);                    \
        }                                                                         \
        CP_COMMIT();                                                              \
    } while (0)

    LOAD_STAGE(0);

    for (int s = 0; s < NKIT; s++) {
        if (s + 1 < NKIT) LOAD_STAGE(s + 1);
        else              CP_COMMIT();               // keep group count uniform
        CP_WAIT1();
        __syncthreads();

        const uint32_t aB = sb + A_BUF(s) * 16384;
        const uint32_t bB = sb + 32768 + (s & 1) * 16384;
#pragma unroll
        for (int k16 = 0; k16 < 4; k16++) {
            uint32_t af[4][4], bf[4][2];
#pragma unroll
            for (int mi = 0; mi < 4; mi++) {
                const int row = wm * 64 + mi * 16 + (lane & 15);
                const uint32_t ad = aB + SWZ(row * 128 + k16 * 32 + (lane >> 4) * 16);
                asm volatile("ldmatrix.sync.aligned.m8n8.x4.shared.b16 {%0,%1,%2,%3}, [%4];"
                    : "=r"(af[mi][0]), "=r"(af[mi][1]), "=r"(af[mi][2]), "=r"(af[mi][3])
                    : "r"(ad));
            }
            // B: one x4.trans per 2 n-tiles.  lane group g = lane>>3:
            //   matrices 0,1 -> (k0-7, k8-15) of tile ni ; 2,3 -> of tile ni+1
#pragma unroll
            for (int ni = 0; ni < 4; ni += 2) {
                const int g  = lane >> 3;
                const int kl = k16 * 16 + (g & 1) * 8 + (lane & 7);
                const int gn = wn * 4 + ni + (g >> 1);
                const uint32_t bd = bB + BSWZ(kl, gn);
                asm volatile("ldmatrix.sync.aligned.m8n8.x4.trans.shared.b16 {%0,%1,%2,%3}, [%4];"
                    : "=r"(bf[ni][0]), "=r"(bf[ni][1]),
                      "=r"(bf[ni + 1][0]), "=r"(bf[ni + 1][1])
                    : "r"(bd));
            }
#pragma unroll
            for (int mi = 0; mi < 4; mi++)
#pragma unroll
                for (int ni = 0; ni < 4; ni++)
                    asm volatile(
                        "mma.sync.aligned.m16n8k16.row.col.f32.bf16.bf16.f32 "
                        "{%0,%1,%2,%3}, {%4,%5,%6,%7}, {%8,%9}, {%0,%1,%2,%3};"
                        : "+f"(acc[mi][ni][0]), "+f"(acc[mi][ni][1]),
                          "+f"(acc[mi][ni][2]), "+f"(acc[mi][ni][3])
                        : "r"(af[mi][0]), "r"(af[mi][1]), "r"(af[mi][2]), "r"(af[mi][3]),
                          "r"(bf[ni][0]), "r"(bf[ni][1]));
        }
        __syncthreads();
    }
#undef LOAD_STAGE

    // epilogue: fp32 stores (c0,c1)=(row, col..col+1), (c2,c3)=row+8
#pragma unroll
    for (int mi = 0; mi < 4; mi++) {
        const int r0 = m0 + wm * 64 + mi * 16 + (lane >> 2);
#pragma unroll
        for (int ni = 0; ni < 4; ni++) {
            const int c = n0 + wn * 32 + ni * 8 + (lane & 3) * 2;
            if (r0 < NNODES)
                *reinterpret_cast<float2*>(C + r0 * LAT + c) =
                    make_float2(acc[mi][ni][0], acc[mi][ni][1]);
            if (r0 + 8 < NNODES)
                *reinterpret_cast<float2*>(C + (r0 + 8) * LAT + c) =
                    make_float2(acc[mi][ni][2], acc[mi][ni][3]);
        }
    }
}

// ============================================================================
// prep: elementwise bf16 hi/lo split of the 6 weight matrices (layout kept [k][n])
// ============================================================================
__global__ __launch_bounds__(256)
void prep_w(const float* __restrict__ Ws, const float* __restrict__ Wn)
{
    const int idx = blockIdx.x * 256 + threadIdx.x;     // < 6*65536
    const int p = idx >> 16, rem = idx & 65535;
    const float* src = (p & 1) ? Wn : Ws;
    const float v = src[(p >> 1) * 65536 + rem];
    const __nv_bfloat16 h = __float2bfloat16(v);
    g_Whi[idx] = h;
    g_Wlo[idx] = __float2bfloat16(v - __bfloat162float(h));
}

// convert fp32 x -> bf16 hi/lo (step-0 input)
__global__ __launch_bounds__(256)
void cvt_x(const float* __restrict__ x)
{
    const int i = (blockIdx.x * 256 + threadIdx.x) * 4;
    const float4 v = *reinterpret_cast<const float4*>(x + i);
    __nv_bfloat16 h0 = __float2bfloat16(v.x), h1 = __float2bfloat16(v.y);
    __nv_bfloat16 h2 = __float2bfloat16(v.z), h3 = __float2bfloat16(v.w);
    __nv_bfloat162 hi0 = {h0, h1}, hi1 = {h2, h3};
    __nv_bfloat162 lo0 = {__float2bfloat16(v.x - __bfloat162float(h0)),
                          __float2bfloat16(v.y - __bfloat162float(h1))};
    __nv_bfloat162 lo1 = {__float2bfloat16(v.z - __bfloat162float(h2)),
                          __float2bfloat16(v.w - __bfloat162float(h3))};
    *reinterpret_cast<__nv_bfloat162*>(g_xhi + i)     = hi0;
    *reinterpret_cast<__nv_bfloat162*>(g_xhi + i + 2) = hi1;
    *reinterpret_cast<__nv_bfloat162*>(g_xlo + i)     = lo0;
    *reinterpret_cast<__nv_bfloat162*>(g_xlo + i + 2) = lo1;
}

// ============================================================================
// combine: h = x + S + bs + bn + (1/6)*sum Nn[nbr]; out = relu(LN(h)*g+b)
// also emits bf16 hi/lo of out for the next step's GEMM (when oxh != null)
// ============================================================================
__global__ __launch_bounds__(64)
void combine_k(const float* __restrict__ x,
               const float* __restrict__ bsv,
               const float* __restrict__ bnv,
               const float* __restrict__ gam,
               const float* __restrict__ bet,
               const int*   __restrict__ nbr,
               float*       __restrict__ out,
               __nv_bfloat16* __restrict__ oxh,
               __nv_bfloat16* __restrict__ oxl)
{
    const int row = blockIdx.x;
    const int t   = threadIdx.x;
    const int j   = t << 2;
    const int base = row * LAT + j;

    const int* nb = nbr + row * KNB;
    const int n0 = nb[0], n1 = nb[1], n2 = nb[2], n3 = nb[3], n4 = nb[4], n5 = nb[5];

    const float4 xv = *reinterpret_cast<const float4*>(x + base);
    const float4 sv = *reinterpret_cast<const float4*>(g_S + base);

    float4 a = *reinterpret_cast<const float4*>(g_Nn + n0 * LAT + j);
    const float4 a1 = *reinterpret_cast<const float4*>(g_Nn + n1 * LAT + j);
    const float4 a2 = *reinterpret_cast<const float4*>(g_Nn + n2 * LAT + j);
    const float4 a3 = *reinterpret_cast<const float4*>(g_Nn + n3 * LAT + j);
    const float4 a4 = *reinterpret_cast<const float4*>(g_Nn + n4 * LAT + j);
    const float4 a5 = *reinterpret_cast<const float4*>(g_Nn + n5 * LAT + j);
    a.x += a1.x + a2.x + a3.x + a4.x + a5.x;
    a.y += a1.y + a2.y + a3.y + a4.y + a5.y;
    a.z += a1.z + a2.z + a3.z + a4.z + a5.z;
    a.w += a1.w + a2.w + a3.w + a4.w + a5.w;

    const float4 bq = *reinterpret_cast<const float4*>(bsv + j);
    const float4 nq = *reinterpret_cast<const float4*>(bnv + j);

    const float inv6 = 1.0f / 6.0f;
    float4 h;
    h.x = xv.x + sv.x + bq.x + nq.x + a.x * inv6;
    h.y = xv.y + sv.y + bq.y + nq.y + a.y * inv6;
    h.z = xv.z + sv.z + bq.z + nq.z + a.z * inv6;
    h.w = xv.w + sv.w + bq.w + nq.w + a.w * inv6;

    float s = h.x + h.y + h.z + h.w;
    float q = fmaf(h.x, h.x, fmaf(h.y, h.y, fmaf(h.z, h.z, h.w * h.w)));
#pragma unroll
    for (int o = 16; o > 0; o >>= 1) {
        s += __shfl_xor_sync(0xffffffffu, s, o);
        q += __shfl_xor_sync(0xffffffffu, q, o);
    }
    __shared__ float sh[4];
    if ((t & 31) == 0) { sh[(t >> 5) * 2] = s; sh[(t >> 5) * 2 + 1] = q; }
    __syncthreads();
    s = sh[0] + sh[2];
    q = sh[1] + sh[3];

    const float mu  = s * (1.0f / LAT);
    const float var = q * (1.0f / LAT) - mu * mu;
    const float inv = rsqrtf(var + LN_EPS);

    const float4 g = *reinterpret_cast<const float4*>(gam + j);
    const float4 b = *reinterpret_cast<const float4*>(bet + j);

    float4 o4;
    o4.x = fmaxf(0.0f, (h.x - mu) * inv * g.x + b.x);
    o4.y = fmaxf(0.0f, (h.y - mu) * inv * g.y + b.y);
    o4.z = fmaxf(0.0f, (h.z - mu) * inv * g.z + b.z);
    o4.w = fmaxf(0.0f, (h.w - mu) * inv * g.w + b.w);
    *reinterpret_cast<float4*>(out + base) = o4;

    if (oxh) {
        __nv_bfloat16 h0 = __float2bfloat16(o4.x), h1 = __float2bfloat16(o4.y);
        __nv_bfloat16 h2 = __float2bfloat16(o4.z), h3 = __float2bfloat16(o4.w);
        __nv_bfloat162 hv0 = {h0, h1}, hv1 = {h2, h3};
        __nv_bfloat162 lv0 = {__float2bfloat16(o4.x - __bfloat162float(h0)),
                              __float2bfloat16(o4.y - __bfloat162float(h1))};
        __nv_bfloat162 lv1 = {__float2bfloat16(o4.z - __bfloat162float(h2)),
                              __float2bfloat16(o4.w - __bfloat162float(h3))};
        *reinterpret_cast<__nv_bfloat162*>(oxh + base)     = hv0;
        *reinterpret_cast<__nv_bfloat162*>(oxh + base + 2) = hv1;
        *reinterpret_cast<__nv_bfloat162*>(oxl + base)     = lv0;
        *reinterpret_cast<__nv_bfloat162*>(oxl + base + 2) = lv1;
    }
}

extern "C" void kernel_launch(void* const* d_in, const int* in_sizes, int n_in,
                              void* d_out, int out_size)
{
    const float* x0  = (const float*)d_in[0];
    const float* Ws  = (const float*)d_in[1];
    const float* bs  = (const float*)d_in[2];
    const float* Wn  = (const float*)d_in[3];
    const float* bn  = (const float*)d_in[4];
    const float* lsc = (const float*)d_in[5];
    const float* lof = (const float*)d_in[6];
    const int*   nbr = (const int*)d_in[7];
    float* out = (float*)d_out;

    float* xbuf = nullptr;
    __nv_bfloat16 *xhi = nullptr, *xlo = nullptr;
    cudaGetSymbolAddress((void**)&xbuf, g_x);
    cudaGetSymbolAddress((void**)&xhi,  g_xhi);
    cudaGetSymbolAddress((void**)&xlo,  g_xlo);

    cudaFuncSetAttribute(gemm_mma, cudaFuncAttributeMaxDynamicSharedMemorySize, GEMM_SMEM);

    const dim3 gg(LAT / BN, NTILES, 2);   // (2, 391, 2)
    const dim3 gb(256);
    const dim3 cg(NNODES);
    const dim3 cb(64);

    prep_w<<<6 * 65536 / 256, 256>>>(Ws, Wn);
    cvt_x<<<NNODES * LAT / 1024, 256>>>(x0);

    // step 0
    gemm_mma<<<gg, gb, GEMM_SMEM>>>(xhi, xlo, 0);
    combine_k<<<cg, cb>>>(x0, bs, bn, lsc, lof, nbr, xbuf, xhi, xlo);
    // step 1
    gemm_mma<<<gg, gb, GEMM_SMEM>>>(xhi, xlo, 2);
    combine_k<<<cg, cb>>>(xbuf, bs + LAT, bn + LAT, lsc + LAT, lof + LAT, nbr, xbuf, xhi, xlo);
    // step 2 (final -> d_out)
    gemm_mma<<<gg, gb, GEMM_SMEM>>>(xhi, xlo, 4);
    combine_k<<<cg, cb>>>(xbuf, bs + 2 * LAT, bn + 2 * LAT, lsc + 2 * LAT, lof + 2 * LAT,
                          nbr, out, (__nv_bfloat16*)nullptr, (__nv_bfloat16*)nullptr);
}

// round 10
// speedup vs baseline: 2.5106x; 1.0218x over previous
#include <cuda_runtime.h>
#include <cuda_bf16.h>
#include <cstdint>

// ProcessorCNN: 3-step sphere GNN.  mma.sync (HMMA) bf16 hi/lo-split GEMM path.
//   C = xhi*Whi + xhi*Wlo + xlo*Whi   (fp32 accum; drops ~2^-18 xlo*Wlo term)
//   Stage order interleaves parts so A tiles are reused on adjacent stages:
//     s=0..7 : (chunk s>>1) x (s odd ? Wlo : Whi)  with A=xhi loaded at even s
//     s=8..11: (chunk s&3)  x Whi                  with A=xlo loaded every s
// Activations live ONLY as bf16 hi/lo pairs between steps (fp32 x eliminated;
// residual reconstructs x = hi + lo, error ~2^-17).
// mean(x[nbr]) @ Wn == (1/6) * sum (x@Wn)[nbr]  -> gather AFTER projection.

#define NNODES 50000
#define LAT    256
#define KNB    6
#define LN_EPS 1e-5f

#define BM 128
#define BN 128
#define BKC 64           // k-chunk per pipeline stage
#define NKIT 12          // 12 stages total
#define NTILES 391       // ceil(50000/128)

// ---- device scratch ----
__device__ float         g_S  [NNODES * LAT];
__device__ float         g_Nn [NNODES * LAT];
__device__ __nv_bfloat16 g_xhi[NNODES * LAT];
__device__ __nv_bfloat16 g_xlo[NNODES * LAT];
__device__ __nv_bfloat16 g_Whi[6 * LAT * LAT];   // [part][k][n]  (original layout)
__device__ __nv_bfloat16 g_Wlo[6 * LAT * LAT];

__device__ __forceinline__ uint32_t smem_u32(const void* p) {
    uint32_t a;
    asm("{ .reg .u64 t; cvta.to.shared.u64 t, %1; cvt.u32.u64 %0, t; }" : "=r"(a) : "l"(p));
    return a;
}
#define SWZ(o) ((o) ^ (((o) >> 3) & 0x70))
// B-tile swizzle: [k][n] rows of 256B (16 granules); rotate low-3 granule bits by k
#define BSWZ(k, gn) ((k) * 256 + ((((gn) & 8) | (((gn) ^ (k)) & 7)) << 4))

__device__ __forceinline__ void cpa16(uint32_t dst, const void* src, uint32_t n) {
    asm volatile("cp.async.cg.shared.global [%0], [%1], 16, %2;"
                 :: "r"(dst), "l"(src), "r"(n) : "memory");
}
#define CP_COMMIT() asm volatile("cp.async.commit_group;" ::: "memory")
#define CP_WAIT1()  asm volatile("cp.async.wait_group 1;" ::: "memory")

// smem: A stages at 0/16384 (128 rows x 64 k, 128B rows, SWZ), B at 32768/49152
// ([k][n]: 64 k-rows x 128 n, 256B rows, BSWZ).  total 64 KB.
#define GEMM_SMEM 65536

// A-buffer parity decoupled from stage parity (reuse on odd s<8)
#define A_BUF(s) (((s) < 8) ? (((s) >> 1) & 1) : ((s) & 1))

// ============================================================================
// GEMM: C[z] = x @ W[z]  (z=0 -> g_S w/ Ws, z=1 -> g_Nn w/ Wn)
// ============================================================================
__global__ __launch_bounds__(256, 2)
void gemm_mma(const __nv_bfloat16* __restrict__ xh,
              const __nv_bfloat16* __restrict__ xl,
              int wbase)
{
    extern __shared__ char smem[];
    const uint32_t sb = smem_u32(smem);
    const int tid = threadIdx.x, lane = tid & 31, wid = tid >> 5;
    const int wm = wid >> 2, wn = wid & 3;          // 2 x 4 warp grid (64x32 tiles)
    const int m0 = blockIdx.y * BM;
    const int n0 = blockIdx.x * BN;
    const __nv_bfloat16* Wh = g_Whi + (wbase + blockIdx.z) * (LAT * LAT);
    const __nv_bfloat16* Wl = g_Wlo + (wbase + blockIdx.z) * (LAT * LAT);
    float* C = blockIdx.z ? g_Nn : g_S;

    float acc[4][4][4];
#pragma unroll
    for (int a = 0; a < 4; a++)
#pragma unroll
        for (int b = 0; b < 4; b++)
#pragma unroll
            for (int c = 0; c < 4; c++) acc[a][b][c] = 0.0f;

    // ---- stage loader (see header comment for the stage schedule) ----
#define LOAD_STAGE(s) do {                                                        \
        const int  _s  = (s);                                                     \
        const int  _ck = (_s < 8) ? (_s >> 1) : (_s & 3);                         \
        const int  _kc = _ck * BKC;                                               \
        const bool _doA = (_s < 8) ? ((_s & 1) == 0) : true;                      \
        const __nv_bfloat16* _Ap = (_s < 8) ? xh : xl;                            \
        const __nv_bfloat16* _Bp = ((_s < 8) && (_s & 1)) ? Wl : Wh;              \
        const uint32_t _aB = sb + A_BUF(_s) * 16384;                              \
        const uint32_t _bB = sb + 32768 + (_s & 1) * 16384;                       \
        if (_doA) {                                                               \
            _Pragma("unroll")                                                     \
            for (int _i = 0; _i < 4; _i++) {                                      \
                const int _idx = tid + _i * 256;                                  \
                const int _r = _idx >> 3, _g = _idx & 7;                          \
                const int _grow = m0 + _r;                                        \
                const int _srow = (_grow < NNODES) ? _grow : 0;                   \
                cpa16(_aB + SWZ(_r * 128 + _g * 16),                              \
                      _Ap + _srow * LAT + _kc + _g * 8,                           \
                      (_grow < NNODES) ? 16u : 0u);                               \
            }                                                                     \
        }                                                                         \
        _Pragma("unroll")                                                         \
        for (int _i = 0; _i < 4; _i++) {                                          \
            const int _idx = tid + _i * 256;                                      \
            const int _k = _idx >> 4, _gn = _idx & 15;                            \
            cpa16(_bB + BSWZ(_k, _gn),                                            \
                  _Bp + (_kc + _k) * LAT + n0 + _gn * 8, 16u);                    \
        }                                                                         \
        CP_COMMIT();                                                              \
    } while (0)

    LOAD_STAGE(0);

    for (int s = 0; s < NKIT; s++) {
        if (s + 1 < NKIT) LOAD_STAGE(s + 1);
        else              CP_COMMIT();               // keep group count uniform
        CP_WAIT1();
        __syncthreads();

        const uint32_t aB = sb + A_BUF(s) * 16384;
        const uint32_t bB = sb + 32768 + (s & 1) * 16384;
#pragma unroll
        for (int k16 = 0; k16 < 4; k16++) {
            uint32_t af[4][4], bf[4][2];
#pragma unroll
            for (int mi = 0; mi < 4; mi++) {
                const int row = wm * 64 + mi * 16 + (lane & 15);
                const uint32_t ad = aB + SWZ(row * 128 + k16 * 32 + (lane >> 4) * 16);
                asm volatile("ldmatrix.sync.aligned.m8n8.x4.shared.b16 {%0,%1,%2,%3}, [%4];"
                    : "=r"(af[mi][0]), "=r"(af[mi][1]), "=r"(af[mi][2]), "=r"(af[mi][3])
                    : "r"(ad));
            }
            // B: one x4.trans per 2 n-tiles.  lane group g = lane>>3:
            //   matrices 0,1 -> (k0-7, k8-15) of tile ni ; 2,3 -> of tile ni+1
#pragma unroll
            for (int ni = 0; ni < 4; ni += 2) {
                const int g  = lane >> 3;
                const int kl = k16 * 16 + (g & 1) * 8 + (lane & 7);
                const int gn = wn * 4 + ni + (g >> 1);
                const uint32_t bd = bB + BSWZ(kl, gn);
                asm volatile("ldmatrix.sync.aligned.m8n8.x4.trans.shared.b16 {%0,%1,%2,%3}, [%4];"
                    : "=r"(bf[ni][0]), "=r"(bf[ni][1]),
                      "=r"(bf[ni + 1][0]), "=r"(bf[ni + 1][1])
                    : "r"(bd));
            }
#pragma unroll
            for (int mi = 0; mi < 4; mi++)
#pragma unroll
                for (int ni = 0; ni < 4; ni++)
                    asm volatile(
                        "mma.sync.aligned.m16n8k16.row.col.f32.bf16.bf16.f32 "
                        "{%0,%1,%2,%3}, {%4,%5,%6,%7}, {%8,%9}, {%0,%1,%2,%3};"
                        : "+f"(acc[mi][ni][0]), "+f"(acc[mi][ni][1]),
                          "+f"(acc[mi][ni][2]), "+f"(acc[mi][ni][3])
                        : "r"(af[mi][0]), "r"(af[mi][1]), "r"(af[mi][2]), "r"(af[mi][3]),
                          "r"(bf[ni][0]), "r"(bf[ni][1]));
        }
        __syncthreads();
    }
#undef LOAD_STAGE

    // epilogue: fp32 stores (c0,c1)=(row, col..col+1), (c2,c3)=row+8
#pragma unroll
    for (int mi = 0; mi < 4; mi++) {
        const int r0 = m0 + wm * 64 + mi * 16 + (lane >> 2);
#pragma unroll
        for (int ni = 0; ni < 4; ni++) {
            const int c = n0 + wn * 32 + ni * 8 + (lane & 3) * 2;
            if (r0 < NNODES)
                *reinterpret_cast<float2*>(C + r0 * LAT + c) =
                    make_float2(acc[mi][ni][0], acc[mi][ni][1]);
            if (r0 + 8 < NNODES)
                *reinterpret_cast<float2*>(C + (r0 + 8) * LAT + c) =
                    make_float2(acc[mi][ni][2], acc[mi][ni][3]);
        }
    }
}

// ============================================================================
// prep: elementwise bf16 hi/lo split of the 6 weight matrices (layout kept [k][n])
// ============================================================================
__global__ __launch_bounds__(256)
void prep_w(const float* __restrict__ Ws, const float* __restrict__ Wn)
{
    const int idx = blockIdx.x * 256 + threadIdx.x;     // < 6*65536
    const int p = idx >> 16, rem = idx & 65535;
    const float* src = (p & 1) ? Wn : Ws;
    const float v = src[(p >> 1) * 65536 + rem];
    const __nv_bfloat16 h = __float2bfloat16(v);
    g_Whi[idx] = h;
    g_Wlo[idx] = __float2bfloat16(v - __bfloat162float(h));
}

// convert fp32 x -> bf16 hi/lo (step-0 input)
__global__ __launch_bounds__(256)
void cvt_x(const float* __restrict__ x)
{
    const int i = (blockIdx.x * 256 + threadIdx.x) * 4;
    const float4 v = *reinterpret_cast<const float4*>(x + i);
    __nv_bfloat16 h0 = __float2bfloat16(v.x), h1 = __float2bfloat16(v.y);
    __nv_bfloat16 h2 = __float2bfloat16(v.z), h3 = __float2bfloat16(v.w);
    __nv_bfloat162 hi0 = {h0, h1}, hi1 = {h2, h3};
    __nv_bfloat162 lo0 = {__float2bfloat16(v.x - __bfloat162float(h0)),
                          __float2bfloat16(v.y - __bfloat162float(h1))};
    __nv_bfloat162 lo1 = {__float2bfloat16(v.z - __bfloat162float(h2)),
                          __float2bfloat16(v.w - __bfloat162float(h3))};
    *reinterpret_cast<__nv_bfloat162*>(g_xhi + i)     = hi0;
    *reinterpret_cast<__nv_bfloat162*>(g_xhi + i + 2) = hi1;
    *reinterpret_cast<__nv_bfloat162*>(g_xlo + i)     = lo0;
    *reinterpret_cast<__nv_bfloat162*>(g_xlo + i + 2) = lo1;
}

// ============================================================================
// combine: h = x + S + bs + bn + (1/6)*sum Nn[nbr]; y = relu(LN(h)*g+b)
//   x comes from x32 (fp32) if non-null, else reconstructed as xhi+xlo.
//   Writes: fp32 out (if non-null) and/or bf16 hi/lo pair (if non-null).
// 128 threads = 2 rows per block; each 64-thread half owns one row.
// ============================================================================
__global__ __launch_bounds__(128)
void combine_k(const float* __restrict__ x32,
               const __nv_bfloat16* __restrict__ xhin,
               const __nv_bfloat16* __restrict__ xlin,
               const float* __restrict__ bsv,
               const float* __restrict__ bnv,
               const float* __restrict__ gam,
               const float* __restrict__ bet,
               const int*   __restrict__ nbr,
               float*       __restrict__ out,
               __nv_bfloat16* __restrict__ oxh,
               __nv_bfloat16* __restrict__ oxl)
{
    const int half = threadIdx.x >> 6;             // 0 or 1
    const int row  = blockIdx.x * 2 + half;
    const int t    = threadIdx.x & 63;
    const int j    = t << 2;
    const int base = row * LAT + j;

    const int* nb = nbr + row * KNB;
    const int n0 = nb[0], n1 = nb[1], n2 = nb[2], n3 = nb[3], n4 = nb[4], n5 = nb[5];

    float4 xv;
    if (x32) {
        xv = *reinterpret_cast<const float4*>(x32 + base);
    } else {
        const __nv_bfloat162 h0 = *reinterpret_cast<const __nv_bfloat162*>(xhin + base);
        const __nv_bfloat162 h1 = *reinterpret_cast<const __nv_bfloat162*>(xhin + base + 2);
        const __nv_bfloat162 l0 = *reinterpret_cast<const __nv_bfloat162*>(xlin + base);
        const __nv_bfloat162 l1 = *reinterpret_cast<const __nv_bfloat162*>(xlin + base + 2);
        xv.x = __bfloat162float(h0.x) + __bfloat162float(l0.x);
        xv.y = __bfloat162float(h0.y) + __bfloat162float(l0.y);
        xv.z = __bfloat162float(h1.x) + __bfloat162float(l1.x);
        xv.w = __bfloat162float(h1.y) + __bfloat162float(l1.y);
    }
    const float4 sv = *reinterpret_cast<const float4*>(g_S + base);

    float4 a = *reinterpret_cast<const float4*>(g_Nn + n0 * LAT + j);
    const float4 a1 = *reinterpret_cast<const float4*>(g_Nn + n1 * LAT + j);
    const float4 a2 = *reinterpret_cast<const float4*>(g_Nn + n2 * LAT + j);
    const float4 a3 = *reinterpret_cast<const float4*>(g_Nn + n3 * LAT + j);
    const float4 a4 = *reinterpret_cast<const float4*>(g_Nn + n4 * LAT + j);
    const float4 a5 = *reinterpret_cast<const float4*>(g_Nn + n5 * LAT + j);
    a.x += a1.x + a2.x + a3.x + a4.x + a5.x;
    a.y += a1.y + a2.y + a3.y + a4.y + a5.y;
    a.z += a1.z + a2.z + a3.z + a4.z + a5.z;
    a.w += a1.w + a2.w + a3.w + a4.w + a5.w;

    const float4 bq = *reinterpret_cast<const float4*>(bsv + j);
    const float4 nq = *reinterpret_cast<const float4*>(bnv + j);

    const float inv6 = 1.0f / 6.0f;
    float4 h;
    h.x = xv.x + sv.x + bq.x + nq.x + a.x * inv6;
    h.y = xv.y + sv.y + bq.y + nq.y + a.y * inv6;
    h.z = xv.z + sv.z + bq.z + nq.z + a.z * inv6;
    h.w = xv.w + sv.w + bq.w + nq.w + a.w * inv6;

    float s = h.x + h.y + h.z + h.w;
    float q = fmaf(h.x, h.x, fmaf(h.y, h.y, fmaf(h.z, h.z, h.w * h.w)));
#pragma unroll
    for (int o = 16; o > 0; o >>= 1) {
        s += __shfl_xor_sync(0xffffffffu, s, o);
        q += __shfl_xor_sync(0xffffffffu, q, o);
    }
    __shared__ float sh[2][4];
    if ((t & 31) == 0) { sh[half][(t >> 5) * 2] = s; sh[half][(t >> 5) * 2 + 1] = q; }
    __syncthreads();
    s = sh[half][0] + sh[half][2];
    q = sh[half][1] + sh[half][3];

    const float mu  = s * (1.0f / LAT);
    const float var = q * (1.0f / LAT) - mu * mu;
    const float inv = rsqrtf(var + LN_EPS);

    const float4 g = *reinterpret_cast<const float4*>(gam + j);
    const float4 b = *reinterpret_cast<const float4*>(bet + j);

    float4 o4;
    o4.x = fmaxf(0.0f, (h.x - mu) * inv * g.x + b.x);
    o4.y = fmaxf(0.0f, (h.y - mu) * inv * g.y + b.y);
    o4.z = fmaxf(0.0f, (h.z - mu) * inv * g.z + b.z);
    o4.w = fmaxf(0.0f, (h.w - mu) * inv * g.w + b.w);

    if (out)
        *reinterpret_cast<float4*>(out + base) = o4;

    if (oxh) {
        __nv_bfloat16 h0 = __float2bfloat16(o4.x), h1 = __float2bfloat16(o4.y);
        __nv_bfloat16 h2 = __float2bfloat16(o4.z), h3 = __float2bfloat16(o4.w);
        __nv_bfloat162 hv0 = {h0, h1}, hv1 = {h2, h3};
        __nv_bfloat162 lv0 = {__float2bfloat16(o4.x - __bfloat162float(h0)),
                              __float2bfloat16(o4.y - __bfloat162float(h1))};
        __nv_bfloat162 lv1 = {__float2bfloat16(o4.z - __bfloat162float(h2)),
                              __float2bfloat16(o4.w - __bfloat162float(h3))};
        *reinterpret_cast<__nv_bfloat162*>(oxh + base)     = hv0;
        *reinterpret_cast<__nv_bfloat162*>(oxh + base + 2) = hv1;
        *reinterpret_cast<__nv_bfloat162*>(oxl + base)     = lv0;
        *reinterpret_cast<__nv_bfloat162*>(oxl + base + 2) = lv1;
    }
}

extern "C" void kernel_launch(void* const* d_in, const int* in_sizes, int n_in,
                              void* d_out, int out_size)
{
    const float* x0  = (const float*)d_in[0];
    const float* Ws  = (const float*)d_in[1];
    const float* bs  = (const float*)d_in[2];
    const float* Wn  = (const float*)d_in[3];
    const float* bn  = (const float*)d_in[4];
    const float* lsc = (const float*)d_in[5];
    const float* lof = (const float*)d_in[6];
    const int*   nbr = (const int*)d_in[7];
    float* out = (float*)d_out;

    __nv_bfloat16 *xhi = nullptr, *xlo = nullptr;
    cudaGetSymbolAddress((void**)&xhi, g_xhi);
    cudaGetSymbolAddress((void**)&xlo, g_xlo);

    cudaFuncSetAttribute(gemm_mma, cudaFuncAttributeMaxDynamicSharedMemorySize, GEMM_SMEM);

    const dim3 gg(LAT / BN, NTILES, 2);   // (2, 391, 2)
    const dim3 gb(256);
    const dim3 cg(NNODES / 2);            // 25000 blocks x 2 rows
    const dim3 cb(128);

    prep_w<<<6 * 65536 / 256, 256>>>(Ws, Wn);
    cvt_x<<<NNODES * LAT / 1024, 256>>>(x0);

    // step 0: residual from fp32 input; emit hi/lo only
    gemm_mma<<<gg, gb, GEMM_SMEM>>>(xhi, xlo, 0);
    combine_k<<<cg, cb>>>(x0, xhi, xlo, bs, bn, lsc, lof, nbr,
                          (float*)nullptr, xhi, xlo);
    // step 1: residual from hi+lo; emit hi/lo only
    gemm_mma<<<gg, gb, GEMM_SMEM>>>(xhi, xlo, 2);
    combine_k<<<cg, cb>>>((const float*)nullptr, xhi, xlo,
                          bs + LAT, bn + LAT, lsc + LAT, lof + LAT, nbr,
                          (float*)nullptr, xhi, xlo);
    // step 2: residual from hi+lo; emit fp32 d_out only
    gemm_mma<<<gg, gb, GEMM_SMEM>>>(xhi, xlo, 4);
    combine_k<<<cg, cb>>>((const float*)nullptr, xhi, xlo,
                          bs + 2 * LAT, bn + 2 * LAT, lsc + 2 * LAT, lof + 2 * LAT, nbr,
                          out, (__nv_bfloat16*)nullptr, (__nv_bfloat16*)nullptr);
}

// round 12
// speedup vs baseline: 3.1739x; 1.2642x over previous
#include <cuda_runtime.h>
#include <cuda_fp16.h>
#include <cstdint>

// ProcessorCNN: 3-step sphere GNN.  mma.sync (HMMA) fp16 2-pass GEMM path.
//   C = xhi*W_h + xlo*W_h   (fp32 accum; W single fp16, x split to ~21 bits)
//   Error ~ x*eps(W) ~ 2^-11  -> predicted end-to-end rel_err ~4.6e-4
//   (calibrated against R8's measured 1.85e-3 for an eps ~2^-9 term).
//   Stage schedule (8 stages): s = (chunk<<1)|part, part 0=xhi 1=xlo.
//     A loaded every stage (A_BUF = s&1); B loaded on even s, reused on odd
//     (B_BUF = (s>>1)&1).
// Activations live ONLY as fp16 hi/lo pairs between steps.
// mean(x[nbr]) @ Wn == (1/6) * sum (x@Wn)[nbr]  -> gather AFTER projection.

#define NNODES 50000
#define LAT    256
#define KNB    6
#define LN_EPS 1e-5f

#define BM 128
#define BN 128
#define BKC 64           // k-chunk per pipeline stage
#define NKIT 8           // 8 stages: 4 chunks x {xhi, xlo}
#define NTILES 391       // ceil(50000/128)

// ---- device scratch ----
__device__ float  g_S  [NNODES * LAT];
__device__ float  g_Nn [NNODES * LAT];
__device__ __half g_xhi[NNODES * LAT];
__device__ __half g_xlo[NNODES * LAT];
__device__ __half g_Whf[6 * LAT * LAT];   // [part][k][n]  fp16 weights

__device__ __forceinline__ uint32_t smem_u32(const void* p) {
    uint32_t a;
    asm("{ .reg .u64 t; cvta.to.shared.u64 t, %1; cvt.u32.u64 %0, t; }" : "=r"(a) : "l"(p));
    return a;
}
#define SWZ(o) ((o) ^ (((o) >> 3) & 0x70))
// B-tile swizzle: [k][n] rows of 256B (16 granules); rotate low-3 granule bits by k
#define BSWZ(k, gn) ((k) * 256 + ((((gn) & 8) | (((gn) ^ (k)) & 7)) << 4))

__device__ __forceinline__ void cpa16(uint32_t dst, const void* src, uint32_t n) {
    asm volatile("cp.async.cg.shared.global [%0], [%1], 16, %2;"
                 :: "r"(dst), "l"(src), "r"(n) : "memory");
}
#define CP_COMMIT() asm volatile("cp.async.commit_group;" ::: "memory")
#define CP_WAIT1()  asm volatile("cp.async.wait_group 1;" ::: "memory")

// smem: A stages at 0/16384 (128 rows x 64 k, 128B rows, SWZ), B at 32768/49152
// ([k][n]: 64 k-rows x 128 n, 256B rows, BSWZ).  total 64 KB.
#define GEMM_SMEM 65536

#define A_BUF(s) ((s) & 1)
#define B_BUF(s) (((s) >> 1) & 1)

// ============================================================================
// GEMM: C[z] = x @ W[z]  (z=0 -> g_S w/ Ws, z=1 -> g_Nn w/ Wn)
// ============================================================================
__global__ __launch_bounds__(256, 2)
void gemm_mma(const __half* __restrict__ xh,
              const __half* __restrict__ xl,
              int wbase)
{
    extern __shared__ char smem[];
    const uint32_t sb = smem_u32(smem);
    const int tid = threadIdx.x, lane = tid & 31, wid = tid >> 5;
    const int wm = wid >> 2, wn = wid & 3;          // 2 x 4 warp grid (64x32 tiles)
    const int m0 = blockIdx.y * BM;
    const int n0 = blockIdx.x * BN;
    const __half* Wf = g_Whf + (wbase + blockIdx.z) * (LAT * LAT);
    float* C = blockIdx.z ? g_Nn : g_S;

    float acc[4][4][4];
#pragma unroll
    for (int a = 0; a < 4; a++)
#pragma unroll
        for (int b = 0; b < 4; b++)
#pragma unroll
            for (int c = 0; c < 4; c++) acc[a][b][c] = 0.0f;

    // ---- stage loader: chunk = s>>1, part = s&1 (0 = xhi, 1 = xlo) ----
#define LOAD_STAGE(s) do {                                                        \
        const int  _s  = (s);                                                     \
        const int  _kc = (_s >> 1) * BKC;                                         \
        const __half* _Ap = (_s & 1) ? xl : xh;                                   \
        const uint32_t _aB = sb + A_BUF(_s) * 16384;                              \
        const uint32_t _bB = sb + 32768 + B_BUF(_s) * 16384;                      \
        _Pragma("unroll")                                                         \
        for (int _i = 0; _i < 4; _i++) {                                          \
            const int _idx = tid + _i * 256;                                      \
            const int _r = _idx >> 3, _g = _idx & 7;                              \
            const int _grow = m0 + _r;                                            \
            const int _srow = (_grow < NNODES) ? _grow : 0;                       \
            cpa16(_aB + SWZ(_r * 128 + _g * 16),                                  \
                  _Ap + _srow * LAT + _kc + _g * 8,                               \
                  (_grow < NNODES) ? 16u : 0u);                                   \
        }                                                                         \
        if ((_s & 1) == 0) {                                                      \
            _Pragma("unroll")                                                     \
            for (int _i = 0; _i < 4; _i++) {                                      \
                const int _idx = tid + _i * 256;                                  \
                const int _k = _idx >> 4, _gn = _idx & 15;                        \
                cpa16(_bB + BSWZ(_k, _gn),                                        \
                      Wf + (_kc + _k) * LAT + n0 + _gn * 8, 16u);                 \
            }                                                                     \
        }                                                                         \
        CP_COMMIT();                                                              \
    } while (0)

    LOAD_STAGE(0);

    for (int s = 0; s < NKIT; s++) {
        if (s + 1 < NKIT) LOAD_STAGE(s + 1);
        else              CP_COMMIT();               // keep group count uniform
        CP_WAIT1();
        __syncthreads();

        const uint32_t aB = sb + A_BUF(s) * 16384;
        const uint32_t bB = sb + 32768 + B_BUF(s) * 16384;
#pragma unroll
        for (int k16 = 0; k16 < 4; k16++) {
            uint32_t af[4][4], bf[4][2];
#pragma unroll
            for (int mi = 0; mi < 4; mi++) {
                const int row = wm * 64 + mi * 16 + (lane & 15);
                const uint32_t ad = aB + SWZ(row * 128 + k16 * 32 + (lane >> 4) * 16);
                asm volatile("ldmatrix.sync.aligned.m8n8.x4.shared.b16 {%0,%1,%2,%3}, [%4];"
                    : "=r"(af[mi][0]), "=r"(af[mi][1]), "=r"(af[mi][2]), "=r"(af[mi][3])
                    : "r"(ad));
            }
            // B: one x4.trans per 2 n-tiles.  lane group g = lane>>3:
            //   matrices 0,1 -> (k0-7, k8-15) of tile ni ; 2,3 -> of tile ni+1
#pragma unroll
            for (int ni = 0; ni < 4; ni += 2) {
                const int g  = lane >> 3;
                const int kl = k16 * 16 + (g & 1) * 8 + (lane & 7);
                const int gn = wn * 4 + ni + (g >> 1);
                const uint32_t bd = bB + BSWZ(kl, gn);
                asm volatile("ldmatrix.sync.aligned.m8n8.x4.trans.shared.b16 {%0,%1,%2,%3}, [%4];"
                    : "=r"(bf[ni][0]), "=r"(bf[ni][1]),
                      "=r"(bf[ni + 1][0]), "=r"(bf[ni + 1][1])
                    : "r"(bd));
            }
#pragma unroll
            for (int mi = 0; mi < 4; mi++)
#pragma unroll
                for (int ni = 0; ni < 4; ni++)
                    asm volatile(
                        "mma.sync.aligned.m16n8k16.row.col.f32.f16.f16.f32 "
                        "{%0,%1,%2,%3}, {%4,%5,%6,%7}, {%8,%9}, {%0,%1,%2,%3};"
                        : "+f"(acc[mi][ni][0]), "+f"(acc[mi][ni][1]),
                          "+f"(acc[mi][ni][2]), "+f"(acc[mi][ni][3])
                        : "r"(af[mi][0]), "r"(af[mi][1]), "r"(af[mi][2]), "r"(af[mi][3]),
                          "r"(bf[ni][0]), "r"(bf[ni][1]));
        }
        __syncthreads();
    }
#undef LOAD_STAGE

    // epilogue: fp32 stores (c0,c1)=(row, col..col+1), (c2,c3)=row+8
#pragma unroll
    for (int mi = 0; mi < 4; mi++) {
        const int r0 = m0 + wm * 64 + mi * 16 + (lane >> 2);
#pragma unroll
        for (int ni = 0; ni < 4; ni++) {
            const int c = n0 + wn * 32 + ni * 8 + (lane & 3) * 2;
            if (r0 < NNODES)
                *reinterpret_cast<float2*>(C + r0 * LAT + c) =
                    make_float2(acc[mi][ni][0], acc[mi][ni][1]);
            if (r0 + 8 < NNODES)
                *reinterpret_cast<float2*>(C + (r0 + 8) * LAT + c) =
                    make_float2(acc[mi][ni][2], acc[mi][ni][3]);
        }
    }
}

// ============================================================================
// prep: fp16 conversion of the 6 weight matrices (layout kept [k][n])
// ============================================================================
__global__ __launch_bounds__(256)
void prep_w(const float* __restrict__ Ws, const float* __restrict__ Wn)
{
    const int idx = blockIdx.x * 256 + threadIdx.x;     // < 6*65536
    const int p = idx >> 16, rem = idx & 65535;
    const float* src = (p & 1) ? Wn : Ws;
    g_Whf[idx] = __float2half(src[(p >> 1) * 65536 + rem]);
}

// convert fp32 x -> fp16 hi/lo (step-0 input)
__global__ __launch_bounds__(256)
void cvt_x(const float* __restrict__ x)
{
    const int i = (blockIdx.x * 256 + threadIdx.x) * 4;
    const float4 v = *reinterpret_cast<const float4*>(x + i);
    __half h0 = __float2half(v.x), h1 = __float2half(v.y);
    __half h2 = __float2half(v.z), h3 = __float2half(v.w);
    __half l0 = __float2half(v.x - __half2float(h0));
    __half l1 = __float2half(v.y - __half2float(h1));
    __half l2 = __float2half(v.z - __half2float(h2));
    __half l3 = __float2half(v.w - __half2float(h3));
    *reinterpret_cast<__half2*>(g_xhi + i)     = __halves2half2(h0, h1);
    *reinterpret_cast<__half2*>(g_xhi + i + 2) = __halves2half2(h2, h3);
    *reinterpret_cast<__half2*>(g_xlo + i)     = __halves2half2(l0, l1);
    *reinterpret_cast<__half2*>(g_xlo + i + 2) = __halves2half2(l2, l3);
}

// ============================================================================
// combine: h = x + S + bs + bn + (1/6)*sum Nn[nbr]; y = relu(LN(h)*g+b)
//   x comes from x32 (fp32) if non-null, else reconstructed as xhi+xlo.
//   Writes: fp32 out (if non-null) and/or fp16 hi/lo pair (if non-null).
// 128 threads = 2 rows per block; each 64-thread half owns one row.
// ============================================================================
__global__ __launch_bounds__(128)
void combine_k(const float* __restrict__ x32,
               const __half* __restrict__ xhin,
               const __half* __restrict__ xlin,
               const float* __restrict__ bsv,
               const float* __restrict__ bnv,
               const float* __restrict__ gam,
               const float* __restrict__ bet,
               const int*   __restrict__ nbr,
               float*       __restrict__ out,
               __half* __restrict__ oxh,
               __half* __restrict__ oxl)
{
    const int half_ = threadIdx.x >> 6;            // 0 or 1
    const int row  = blockIdx.x * 2 + half_;
    const int t    = threadIdx.x & 63;
    const int j    = t << 2;
    const int base = row * LAT + j;

    const int* nb = nbr + row * KNB;
    const int n0 = nb[0], n1 = nb[1], n2 = nb[2], n3 = nb[3], n4 = nb[4], n5 = nb[5];

    float4 xv;
    if (x32) {
        xv = *reinterpret_cast<const float4*>(x32 + base);
    } else {
        const __half2 h0 = *reinterpret_cast<const __half2*>(xhin + base);
        const __half2 h1 = *reinterpret_cast<const __half2*>(xhin + base + 2);
        const __half2 l0 = *reinterpret_cast<const __half2*>(xlin + base);
        const __half2 l1 = *reinterpret_cast<const __half2*>(xlin + base + 2);
        xv.x = __half2float(h0.x) + __half2float(l0.x);
        xv.y = __half2float(h0.y) + __half2float(l0.y);
        xv.z = __half2float(h1.x) + __half2float(l1.x);
        xv.w = __half2float(h1.y) + __half2float(l1.y);
    }
    const float4 sv = *reinterpret_cast<const float4*>(g_S + base);

    float4 a = *reinterpret_cast<const float4*>(g_Nn + n0 * LAT + j);
    const float4 a1 = *reinterpret_cast<const float4*>(g_Nn + n1 * LAT + j);
    const float4 a2 = *reinterpret_cast<const float4*>(g_Nn + n2 * LAT + j);
    const float4 a3 = *reinterpret_cast<const float4*>(g_Nn + n3 * LAT + j);
    const float4 a4 = *reinterpret_cast<const float4*>(g_Nn + n4 * LAT + j);
    const float4 a5 = *reinterpret_cast<const float4*>(g_Nn + n5 * LAT + j);
    a.x += a1.x + a2.x + a3.x + a4.x + a5.x;
    a.y += a1.y + a2.y + a3.y + a4.y + a5.y;
    a.z += a1.z + a2.z + a3.z + a4.z + a5.z;
    a.w += a1.w + a2.w + a3.w + a4.w + a5.w;

    const float4 bq = *reinterpret_cast<const float4*>(bsv + j);
    const float4 nq = *reinterpret_cast<const float4*>(bnv + j);

    const float inv6 = 1.0f / 6.0f;
    float4 h;
    h.x = xv.x + sv.x + bq.x + nq.x + a.x * inv6;
    h.y = xv.y + sv.y + bq.y + nq.y + a.y * inv6;
    h.z = xv.z + sv.z + bq.z + nq.z + a.z * inv6;
    h.w = xv.w + sv.w + bq.w + nq.w + a.w * inv6;

    float s = h.x + h.y + h.z + h.w;
    float q = fmaf(h.x, h.x, fmaf(h.y, h.y, fmaf(h.z, h.z, h.w * h.w)));
#pragma unroll
    for (int o = 16; o > 0; o >>= 1) {
        s += __shfl_xor_sync(0xffffffffu, s, o);
        q += __shfl_xor_sync(0xffffffffu, q, o);
    }
    __shared__ float sh[2][4];
    if ((t & 31) == 0) { sh[half_][(t >> 5) * 2] = s; sh[half_][(t >> 5) * 2 + 1] = q; }
    __syncthreads();
    s = sh[half_][0] + sh[half_][2];
    q = sh[half_][1] + sh[half_][3];

    const float mu  = s * (1.0f / LAT);
    const float var = q * (1.0f / LAT) - mu * mu;
    const float inv = rsqrtf(var + LN_EPS);

    const float4 g = *reinterpret_cast<const float4*>(gam + j);
    const float4 b = *reinterpret_cast<const float4*>(bet + j);

    float4 o4;
    o4.x = fmaxf(0.0f, (h.x - mu) * inv * g.x + b.x);
    o4.y = fmaxf(0.0f, (h.y - mu) * inv * g.y + b.y);
    o4.z = fmaxf(0.0f, (h.z - mu) * inv * g.z + b.z);
    o4.w = fmaxf(0.0f, (h.w - mu) * inv * g.w + b.w);

    if (out)
        *reinterpret_cast<float4*>(out + base) = o4;

    if (oxh) {
        __half h0 = __float2half(o4.x), h1 = __float2half(o4.y);
        __half h2 = __float2half(o4.z), h3 = __float2half(o4.w);
        __half l0 = __float2half(o4.x - __half2float(h0));
        __half l1 = __float2half(o4.y - __half2float(h1));
        __half l2 = __float2half(o4.z - __half2float(h2));
        __half l3 = __float2half(o4.w - __half2float(h3));
        *reinterpret_cast<__half2*>(oxh + base)     = __halves2half2(h0, h1);
        *reinterpret_cast<__half2*>(oxh + base + 2) = __halves2half2(h2, h3);
        *reinterpret_cast<__half2*>(oxl + base)     = __halves2half2(l0, l1);
        *reinterpret_cast<__half2*>(oxl + base + 2) = __halves2half2(l2, l3);
    }
}

extern "C" void kernel_launch(void* const* d_in, const int* in_sizes, int n_in,
                              void* d_out, int out_size)
{
    const float* x0  = (const float*)d_in[0];
    const float* Ws  = (const float*)d_in[1];
    const float* bs  = (const float*)d_in[2];
    const float* Wn  = (const float*)d_in[3];
    const float* bn  = (const float*)d_in[4];
    const float* lsc = (const float*)d_in[5];
    const float* lof = (const float*)d_in[6];
    const int*   nbr = (const int*)d_in[7];
    float* out = (float*)d_out;

    __half *xhi = nullptr, *xlo = nullptr;
    cudaGetSymbolAddress((void**)&xhi, g_xhi);
    cudaGetSymbolAddress((void**)&xlo, g_xlo);

    cudaFuncSetAttribute(gemm_mma, cudaFuncAttributeMaxDynamicSharedMemorySize, GEMM_SMEM);

    const dim3 gg(LAT / BN, NTILES, 2);   // (2, 391, 2)
    const dim3 gb(256);
    const dim3 cg(NNODES / 2);            // 25000 blocks x 2 rows
    const dim3 cb(128);

    prep_w<<<6 * 65536 / 256, 256>>>(Ws, Wn);
    cvt_x<<<NNODES * LAT / 1024, 256>>>(x0);

    // step 0: residual from fp32 input; emit hi/lo only
    gemm_mma<<<gg, gb, GEMM_SMEM>>>(xhi, xlo, 0);
    combine_k<<<cg, cb>>>(x0, xhi, xlo, bs, bn, lsc, lof, nbr,
                          (float*)nullptr, xhi, xlo);
    // step 1: residual from hi+lo; emit hi/lo only
    gemm_mma<<<gg, gb, GEMM_SMEM>>>(xhi, xlo, 2);
    combine_k<<<cg, cb>>>((const float*)nullptr, xhi, xlo,
                          bs + LAT, bn + LAT, lsc + LAT, lof + LAT, nbr,
                          (float*)nullptr, xhi, xlo);
    // step 2: residual from hi+lo; emit fp32 d_out only
    gemm_mma<<<gg, gb, GEMM_SMEM>>>(xhi, xlo, 4);
    combine_k<<<cg, cb>>>((const float*)nullptr, xhi, xlo,
                          bs + 2 * LAT, bn + 2 * LAT, lsc + 2 * LAT, lof + 2 * LAT, nbr,
                          out, (__half*)nullptr, (__half*)nullptr);
}

// round 15
// speedup vs baseline: 4.1353x; 1.3029x over previous
#include <cuda_runtime.h>
#include <cuda_fp16.h>
#include <cstdint>

// ProcessorCNN: 3-step sphere GNN.  mma.sync (HMMA) fp16 single-pass GEMM.
//   C = xhi * W_h   (fp32 accum; both operands fp16)
//   Error = dx*W + x*dW, both ~2^-11 -> predicted rel_err ~4-5.5e-4
//   (x*dW alone measured 2.66e-4 end-to-end in R12's 2-pass kernel).
//   The inter-step residual keeps full ~21-bit precision: combine carries
//   x as an fp16 hi/lo pair and reconstructs x = hi + lo; only the GEMM
//   input is truncated to hi.
// mean(x[nbr]) @ Wn == (1/6) * sum (x@Wn)[nbr]  -> gather AFTER projection.

#define NNODES 50000
#define LAT    256
#define KNB    6
#define LN_EPS 1e-5f

#define BM 128
#define BN 128
#define BKC 64           // k-chunk per pipeline stage
#define NKIT 4           // 4 chunks of 64 = K 256
#define NTILES 391       // ceil(50000/128)

// ---- device scratch ----
__device__ float  g_S  [NNODES * LAT];
__device__ float  g_Nn [NNODES * LAT];
__device__ __half g_xhi[NNODES * LAT];
__device__ __half g_xlo[NNODES * LAT];
__device__ __half g_Whf[6 * LAT * LAT];   // [part][k][n]  fp16 weights

__device__ __forceinline__ uint32_t smem_u32(const void* p) {
    uint32_t a;
    asm("{ .reg .u64 t; cvta.to.shared.u64 t, %1; cvt.u32.u64 %0, t; }" : "=r"(a) : "l"(p));
    return a;
}
#define SWZ(o) ((o) ^ (((o) >> 3) & 0x70))
// B-tile swizzle: [k][n] rows of 256B (16 granules); rotate low-3 granule bits by k
#define BSWZ(k, gn) ((k) * 256 + ((((gn) & 8) | (((gn) ^ (k)) & 7)) << 4))

__device__ __forceinline__ void cpa16(uint32_t dst, const void* src, uint32_t n) {
    asm volatile("cp.async.cg.shared.global [%0], [%1], 16, %2;"
                 :: "r"(dst), "l"(src), "r"(n) : "memory");
}
#define CP_COMMIT() asm volatile("cp.async.commit_group;" ::: "memory")
#define CP_WAIT1()  asm volatile("cp.async.wait_group 1;" ::: "memory")

// smem: A stages at 0/16384 (128 rows x 64 k, 128B rows, SWZ), B at 32768/49152
// ([k][n]: 64 k-rows x 128 n, 256B rows, BSWZ).  total 64 KB.
#define GEMM_SMEM 65536

// ============================================================================
// GEMM: C[z] = xhi @ W[z]  (z=0 -> g_S w/ Ws, z=1 -> g_Nn w/ Wn)
// ============================================================================
__global__ __launch_bounds__(256, 2)
void gemm_mma(const __half* __restrict__ xh, int wbase)
{
    extern __shared__ char smem[];
    const uint32_t sb = smem_u32(smem);
    const int tid = threadIdx.x, lane = tid & 31, wid = tid >> 5;
    const int wm = wid >> 2, wn = wid & 3;          // 2 x 4 warp grid (64x32 tiles)
    const int m0 = blockIdx.y * BM;
    const int n0 = blockIdx.x * BN;
    const __half* Wf = g_Whf + (wbase + blockIdx.z) * (LAT * LAT);
    float* C = blockIdx.z ? g_Nn : g_S;

    float acc[4][4][4];
#pragma unroll
    for (int a = 0; a < 4; a++)
#pragma unroll
        for (int b = 0; b < 4; b++)
#pragma unroll
            for (int c = 0; c < 4; c++) acc[a][b][c] = 0.0f;

    // ---- stage loader: chunk s, buffers s&1 ----
#define LOAD_STAGE(s) do {                                                        \
        const int  _s  = (s);                                                     \
        const int  _kc = _s * BKC;                                                \
        const uint32_t _aB = sb + (_s & 1) * 16384;                               \
        const uint32_t _bB = sb + 32768 + (_s & 1) * 16384;                       \
        _Pragma("unroll")                                                         \
        for (int _i = 0; _i < 4; _i++) {                                          \
            const int _idx = tid + _i * 256;                                      \
            const int _r = _idx >> 3, _g = _idx & 7;                              \
            const int _grow = m0 + _r;                                            \
            const int _srow = (_grow < NNODES) ? _grow : 0;                       \
            cpa16(_aB + SWZ(_r * 128 + _g * 16),                                  \
                  xh + _srow * LAT + _kc + _g * 8,                                \
                  (_grow < NNODES) ? 16u : 0u);                                   \
        }                                                                         \
        _Pragma("unroll")                                                         \
        for (int _i = 0; _i < 4; _i++) {                                          \
            const int _idx = tid + _i * 256;                                      \
            const int _k = _idx >> 4, _gn = _idx & 15;                            \
            cpa16(_bB + BSWZ(_k, _gn),                                            \
                  Wf + (_kc + _k) * LAT + n0 + _gn * 8, 16u);                     \
        }                                                                         \
        CP_COMMIT();                                                              \
    } while (0)

    LOAD_STAGE(0);

    for (int s = 0; s < NKIT; s++) {
        if (s + 1 < NKIT) LOAD_STAGE(s + 1);
        else              CP_COMMIT();               // keep group count uniform
        CP_WAIT1();
        __syncthreads();

        const uint32_t aB = sb + (s & 1) * 16384;
        const uint32_t bB = sb + 32768 + (s & 1) * 16384;
#pragma unroll
        for (int k16 = 0; k16 < 4; k16++) {
            uint32_t af[4][4], bf[4][2];
#pragma unroll
            for (int mi = 0; mi < 4; mi++) {
                const int row = wm * 64 + mi * 16 + (lane & 15);
                const uint32_t ad = aB + SWZ(row * 128 + k16 * 32 + (lane >> 4) * 16);
                asm volatile("ldmatrix.sync.aligned.m8n8.x4.shared.b16 {%0,%1,%2,%3}, [%4];"
                    : "=r"(af[mi][0]), "=r"(af[mi][1]), "=r"(af[mi][2]), "=r"(af[mi][3])
                    : "r"(ad));
            }
            // B: one x4.trans per 2 n-tiles.  lane group g = lane>>3:
            //   matrices 0,1 -> (k0-7, k8-15) of tile ni ; 2,3 -> of tile ni+1
#pragma unroll
            for (int ni = 0; ni < 4; ni += 2) {
                const int g  = lane >> 3;
                const int kl = k16 * 16 + (g & 1) * 8 + (lane & 7);
                const int gn = wn * 4 + ni + (g >> 1);
                const uint32_t bd = bB + BSWZ(kl, gn);
                asm volatile("ldmatrix.sync.aligned.m8n8.x4.trans.shared.b16 {%0,%1,%2,%3}, [%4];"
                    : "=r"(bf[ni][0]), "=r"(bf[ni][1]),
                      "=r"(bf[ni + 1][0]), "=r"(bf[ni + 1][1])
                    : "r"(bd));
            }
#pragma unroll
            for (int mi = 0; mi < 4; mi++)
#pragma unroll
                for (int ni = 0; ni < 4; ni++)
                    asm volatile(
                        "mma.sync.aligned.m16n8k16.row.col.f32.f16.f16.f32 "
                        "{%0,%1,%2,%3}, {%4,%5,%6,%7}, {%8,%9}, {%0,%1,%2,%3};"
                        : "+f"(acc[mi][ni][0]), "+f"(acc[mi][ni][1]),
                          "+f"(acc[mi][ni][2]), "+f"(acc[mi][ni][3])
                        : "r"(af[mi][0]), "r"(af[mi][1]), "r"(af[mi][2]), "r"(af[mi][3]),
                          "r"(bf[ni][0]), "r"(bf[ni][1]));
        }
        __syncthreads();
    }
#undef LOAD_STAGE

    // epilogue: fp32 stores (c0,c1)=(row, col..col+1), (c2,c3)=row+8
#pragma unroll
    for (int mi = 0; mi < 4; mi++) {
        const int r0 = m0 + wm * 64 + mi * 16 + (lane >> 2);
#pragma unroll
        for (int ni = 0; ni < 4; ni++) {
            const int c = n0 + wn * 32 + ni * 8 + (lane & 3) * 2;
            if (r0 < NNODES)
                *reinterpret_cast<float2*>(C + r0 * LAT + c) =
                    make_float2(acc[mi][ni][0], acc[mi][ni][1]);
            if (r0 + 8 < NNODES)
                *reinterpret_cast<float2*>(C + (r0 + 8) * LAT + c) =
                    make_float2(acc[mi][ni][2], acc[mi][ni][3]);
        }
    }
}

// ============================================================================
// prep: fp16 conversion of the 6 weight matrices (layout kept [k][n])
// ============================================================================
__global__ __launch_bounds__(256)
void prep_w(const float* __restrict__ Ws, const float* __restrict__ Wn)
{
    const int idx = blockIdx.x * 256 + threadIdx.x;     // < 6*65536
    const int p = idx >> 16, rem = idx & 65535;
    const float* src = (p & 1) ? Wn : Ws;
    g_Whf[idx] = __float2half(src[(p >> 1) * 65536 + rem]);
}

// convert fp32 x -> fp16 hi/lo (step-0 input)
__global__ __launch_bounds__(256)
void cvt_x(const float* __restrict__ x)
{
    const int i = (blockIdx.x * 256 + threadIdx.x) * 4;
    const float4 v = *reinterpret_cast<const float4*>(x + i);
    __half h0 = __float2half(v.x), h1 = __float2half(v.y);
    __half h2 = __float2half(v.z), h3 = __float2half(v.w);
    __half l0 = __float2half(v.x - __half2float(h0));
    __half l1 = __float2half(v.y - __half2float(h1));
    __half l2 = __float2half(v.z - __half2float(h2));
    __half l3 = __float2half(v.w - __half2float(h3));
    *reinterpret_cast<__half2*>(g_xhi + i)     = __halves2half2(h0, h1);
    *reinterpret_cast<__half2*>(g_xhi + i + 2) = __halves2half2(h2, h3);
    *reinterpret_cast<__half2*>(g_xlo + i)     = __halves2half2(l0, l1);
    *reinterpret_cast<__half2*>(g_xlo + i + 2) = __halves2half2(l2, l3);
}

// ============================================================================
// combine: h = x + S + bs + bn + (1/6)*sum Nn[nbr]; y = relu(LN(h)*g+b)
//   x comes from x32 (fp32) if non-null, else reconstructed as xhi+xlo.
//   Writes: fp32 out (if non-null) and/or fp16 hi/lo pair (if non-null).
// 128 threads = 2 rows per block; each 64-thread half owns one row.
// ============================================================================
__global__ __launch_bounds__(128)
void combine_k(const float* __restrict__ x32,
               const __half* __restrict__ xhin,
               const __half* __restrict__ xlin,
               const float* __restrict__ bsv,
               const float* __restrict__ bnv,
               const float* __restrict__ gam,
               const float* __restrict__ bet,
               const int*   __restrict__ nbr,
               float*       __restrict__ out,
               __half* __restrict__ oxh,
               __half* __restrict__ oxl)
{
    const int half_ = threadIdx.x >> 6;            // 0 or 1
    const int row  = blockIdx.x * 2 + half_;
    const int t    = threadIdx.x & 63;
    const int j    = t << 2;
    const int base = row * LAT + j;

    const int* nb = nbr + row * KNB;
    const int n0 = nb[0], n1 = nb[1], n2 = nb[2], n3 = nb[3], n4 = nb[4], n5 = nb[5];

    float4 xv;
    if (x32) {
        xv = *reinterpret_cast<const float4*>(x32 + base);
    } else {
        const __half2 h0 = *reinterpret_cast<const __half2*>(xhin + base);
        const __half2 h1 = *reinterpret_cast<const __half2*>(xhin + base + 2);
        const __half2 l0 = *reinterpret_cast<const __half2*>(xlin + base);
        const __half2 l1 = *reinterpret_cast<const __half2*>(xlin + base + 2);
        xv.x = __half2float(h0.x) + __half2float(l0.x);
        xv.y = __half2float(h0.y) + __half2float(l0.y);
        xv.z = __half2float(h1.x) + __half2float(l1.x);
        xv.w = __half2float(h1.y) + __half2float(l1.y);
    }
    const float4 sv = *reinterpret_cast<const float4*>(g_S + base);

    float4 a = *reinterpret_cast<const float4*>(g_Nn + n0 * LAT + j);
    const float4 a1 = *reinterpret_cast<const float4*>(g_Nn + n1 * LAT + j);
    const float4 a2 = *reinterpret_cast<const float4*>(g_Nn + n2 * LAT + j);
    const float4 a3 = *reinterpret_cast<const float4*>(g_Nn + n3 * LAT + j);
    const float4 a4 = *reinterpret_cast<const float4*>(g_Nn + n4 * LAT + j);
    const float4 a5 = *reinterpret_cast<const float4*>(g_Nn + n5 * LAT + j);
    a.x += a1.x + a2.x + a3.x + a4.x + a5.x;
    a.y += a1.y + a2.y + a3.y + a4.y + a5.y;
    a.z += a1.z + a2.z + a3.z + a4.z + a5.z;
    a.w += a1.w + a2.w + a3.w + a4.w + a5.w;

    const float4 bq = *reinterpret_cast<const float4*>(bsv + j);
    const float4 nq = *reinterpret_cast<const float4*>(bnv + j);

    const float inv6 = 1.0f / 6.0f;
    float4 h;
    h.x = xv.x + sv.x + bq.x + nq.x + a.x * inv6;
    h.y = xv.y + sv.y + bq.y + nq.y + a.y * inv6;
    h.z = xv.z + sv.z + bq.z + nq.z + a.z * inv6;
    h.w = xv.w + sv.w + bq.w + nq.w + a.w * inv6;

    float s = h.x + h.y + h.z + h.w;
    float q = fmaf(h.x, h.x, fmaf(h.y, h.y, fmaf(h.z, h.z, h.w * h.w)));
#pragma unroll
    for (int o = 16; o > 0; o >>= 1) {
        s += __shfl_xor_sync(0xffffffffu, s, o);
        q += __shfl_xor_sync(0xffffffffu, q, o);
    }
    __shared__ float sh[2][4];
    if ((t & 31) == 0) { sh[half_][(t >> 5) * 2] = s; sh[half_][(t >> 5) * 2 + 1] = q; }
    __syncthreads();
    s = sh[half_][0] + sh[half_][2];
    q = sh[half_][1] + sh[half_][3];

    const float mu  = s * (1.0f / LAT);
    const float var = q * (1.0f / LAT) - mu * mu;
    const float inv = rsqrtf(var + LN_EPS);

    const float4 g = *reinterpret_cast<const float4*>(gam + j);
    const float4 b = *reinterpret_cast<const float4*>(bet + j);

    float4 o4;
    o4.x = fmaxf(0.0f, (h.x - mu) * inv * g.x + b.x);
    o4.y = fmaxf(0.0f, (h.y - mu) * inv * g.y + b.y);
    o4.z = fmaxf(0.0f, (h.z - mu) * inv * g.z + b.z);
    o4.w = fmaxf(0.0f, (h.w - mu) * inv * g.w + b.w);

    if (out)
        *reinterpret_cast<float4*>(out + base) = o4;

    if (oxh) {
        __half h0 = __float2half(o4.x), h1 = __float2half(o4.y);
        __half h2 = __float2half(o4.z), h3 = __float2half(o4.w);
        __half l0 = __float2half(o4.x - __half2float(h0));
        __half l1 = __float2half(o4.y - __half2float(h1));
        __half l2 = __float2half(o4.z - __half2float(h2));
        __half l3 = __float2half(o4.w - __half2float(h3));
        *reinterpret_cast<__half2*>(oxh + base)     = __halves2half2(h0, h1);
        *reinterpret_cast<__half2*>(oxh + base + 2) = __halves2half2(h2, h3);
        *reinterpret_cast<__half2*>(oxl + base)     = __halves2half2(l0, l1);
        *reinterpret_cast<__half2*>(oxl + base + 2) = __halves2half2(l2, l3);
    }
}

extern "C" void kernel_launch(void* const* d_in, const int* in_sizes, int n_in,
                              void* d_out, int out_size)
{
    const float* x0  = (const float*)d_in[0];
    const float* Ws  = (const float*)d_in[1];
    const float* bs  = (const float*)d_in[2];
    const float* Wn  = (const float*)d_in[3];
    const float* bn  = (const float*)d_in[4];
    const float* lsc = (const float*)d_in[5];
    const float* lof = (const float*)d_in[6];
    const int*   nbr = (const int*)d_in[7];
    float* out = (float*)d_out;

    __half *xhi = nullptr, *xlo = nullptr;
    cudaGetSymbolAddress((void**)&xhi, g_xhi);
    cudaGetSymbolAddress((void**)&xlo, g_xlo);

    cudaFuncSetAttribute(gemm_mma, cudaFuncAttributeMaxDynamicSharedMemorySize, GEMM_SMEM);

    const dim3 gg(LAT / BN, NTILES, 2);   // (2, 391, 2)
    const dim3 gb(256);
    const dim3 cg(NNODES / 2);            // 25000 blocks x 2 rows
    const dim3 cb(128);

    prep_w<<<6 * 65536 / 256, 256>>>(Ws, Wn);
    cvt_x<<<NNODES * LAT / 1024, 256>>>(x0);

    // step 0: residual from fp32 input; emit hi/lo only
    gemm_mma<<<gg, gb, GEMM_SMEM>>>(xhi, 0);
    combine_k<<<cg, cb>>>(x0, xhi, xlo, bs, bn, lsc, lof, nbr,
                          (float*)nullptr, xhi, xlo);
    // step 1: residual from hi+lo; emit hi/lo only
    gemm_mma<<<gg, gb, GEMM_SMEM>>>(xhi, 2);
    combine_k<<<cg, cb>>>((const float*)nullptr, xhi, xlo,
                          bs + LAT, bn + LAT, lsc + LAT, lof + LAT, nbr,
                          (float*)nullptr, xhi, xlo);
    // step 2: residual from hi+lo; emit fp32 d_out only
    gemm_mma<<<gg, gb, GEMM_SMEM>>>(xhi, 4);
    combine_k<<<cg, cb>>>((const float*)nullptr, xhi, xlo,
                          bs + 2 * LAT, bn + 2 * LAT, lsc + 2 * LAT, lof + 2 * LAT, nbr,
                          out, (__half*)nullptr, (__half*)nullptr);
}

// round 17
// speedup vs baseline: 4.2860x; 1.0364x over previous
#include <cuda_runtime.h>
#include <cuda_fp16.h>
#include <cstdint>

// ProcessorCNN: 3-step sphere GNN.  mma.sync (HMMA) fp16 single-pass GEMM.
//   C = xhi * W_h   (fp32 accum; both operands fp16; C stored fp16)
//   Error terms: dx*W, x*dW (measured together 3.63e-4 end-to-end) plus
//   fp16 storage rounding of S/Nn (~2^-11) -> predicted rel_err ~4.5-6.5e-4.
//   The inter-step residual keeps ~21-bit precision: combine carries x as an
//   fp16 hi/lo pair and reconstructs x = hi + lo.
// mean(x[nbr]) @ Wn == (1/6) * sum (x@Wn)[nbr]  -> gather AFTER projection.

#define NNODES 50000
#define LAT    256
#define KNB    6
#define LN_EPS 1e-5f

#define BM 128
#define BN 128
#define BKC 64           // k-chunk per pipeline stage
#define NKIT 4           // 4 chunks of 64 = K 256
#define NTILES 391       // ceil(50000/128)

// ---- device scratch ----
__device__ __half g_S  [NNODES * LAT];
__device__ __half g_Nn [NNODES * LAT];
__device__ __half g_xhi[NNODES * LAT];
__device__ __half g_xlo[NNODES * LAT];
__device__ __half g_Whf[6 * LAT * LAT];   // [part][k][n]  fp16 weights

__device__ __forceinline__ uint32_t smem_u32(const void* p) {
    uint32_t a;
    asm("{ .reg .u64 t; cvta.to.shared.u64 t, %1; cvt.u32.u64 %0, t; }" : "=r"(a) : "l"(p));
    return a;
}
#define SWZ(o) ((o) ^ (((o) >> 3) & 0x70))
// B-tile swizzle: [k][n] rows of 256B (16 granules); rotate low-3 granule bits by k
#define BSWZ(k, gn) ((k) * 256 + ((((gn) & 8) | (((gn) ^ (k)) & 7)) << 4))

__device__ __forceinline__ void cpa16(uint32_t dst, const void* src, uint32_t n) {
    asm volatile("cp.async.cg.shared.global [%0], [%1], 16, %2;"
                 :: "r"(dst), "l"(src), "r"(n) : "memory");
}
#define CP_COMMIT() asm volatile("cp.async.commit_group;" ::: "memory")
#define CP_WAIT1()  asm volatile("cp.async.wait_group 1;" ::: "memory")

// smem: A stages at 0/16384 (128 rows x 64 k, 128B rows, SWZ), B at 32768/49152
// ([k][n]: 64 k-rows x 128 n, 256B rows, BSWZ).  total 64 KB.
#define GEMM_SMEM 65536

// ============================================================================
// GEMM: C[z] = xhi @ W[z]  (z=0 -> g_S w/ Ws, z=1 -> g_Nn w/ Wn), fp16 out
// ============================================================================
__global__ __launch_bounds__(256, 2)
void gemm_mma(const __half* __restrict__ xh, int wbase)
{
    extern __shared__ char smem[];
    const uint32_t sb = smem_u32(smem);
    const int tid = threadIdx.x, lane = tid & 31, wid = tid >> 5;
    const int wm = wid >> 2, wn = wid & 3;          // 2 x 4 warp grid (64x32 tiles)
    const int m0 = blockIdx.y * BM;
    const int n0 = blockIdx.x * BN;
    const __half* Wf = g_Whf + (wbase + blockIdx.z) * (LAT * LAT);
    __half* C = blockIdx.z ? g_Nn : g_S;

    float acc[4][4][4];
#pragma unroll
    for (int a = 0; a < 4; a++)
#pragma unroll
        for (int b = 0; b < 4; b++)
#pragma unroll
            for (int c = 0; c < 4; c++) acc[a][b][c] = 0.0f;

    // ---- stage loader: chunk s, buffers s&1 ----
#define LOAD_STAGE(s) do {                                                        \
        const int  _s  = (s);                                                     \
        const int  _kc = _s * BKC;                                                \
        const uint32_t _aB = sb + (_s & 1) * 16384;                               \
        const uint32_t _bB = sb + 32768 + (_s & 1) * 16384;                       \
        _Pragma("unroll")                                                         \
        for (int _i = 0; _i < 4; _i++) {                                          \
            const int _idx = tid + _i * 256;                                      \
            const int _r = _idx >> 3, _g = _idx & 7;                              \
            const int _grow = m0 + _r;                                            \
            const int _srow = (_grow < NNODES) ? _grow : 0;                       \
            cpa16(_aB + SWZ(_r * 128 + _g * 16),                                  \
                  xh + _srow * LAT + _kc + _g * 8,                                \
                  (_grow < NNODES) ? 16u : 0u);                                   \
        }                                                                         \
        _Pragma("unroll")                                                         \
        for (int _i = 0; _i < 4; _i++) {                                          \
            const int _idx = tid + _i * 256;                                      \
            const int _k = _idx >> 4, _gn = _idx & 15;                            \
            cpa16(_bB + BSWZ(_k, _gn),                                            \
                  Wf + (_kc + _k) * LAT + n0 + _gn * 8, 16u);                     \
        }                                                                         \
        CP_COMMIT();                                                              \
    } while (0)

    LOAD_STAGE(0);

    for (int s = 0; s < NKIT; s++) {
        if (s + 1 < NKIT) LOAD_STAGE(s + 1);
        else              CP_COMMIT();               // keep group count uniform
        CP_WAIT1();
        __syncthreads();

        const uint32_t aB = sb + (s & 1) * 16384;
        const uint32_t bB = sb + 32768 + (s & 1) * 16384;
#pragma unroll
        for (int k16 = 0; k16 < 4; k16++) {
            uint32_t af[4][4], bf[4][2];
#pragma unroll
            for (int mi = 0; mi < 4; mi++) {
                const int row = wm * 64 + mi * 16 + (lane & 15);
                const uint32_t ad = aB + SWZ(row * 128 + k16 * 32 + (lane >> 4) * 16);
                asm volatile("ldmatrix.sync.aligned.m8n8.x4.shared.b16 {%0,%1,%2,%3}, [%4];"
                    : "=r"(af[mi][0]), "=r"(af[mi][1]), "=r"(af[mi][2]), "=r"(af[mi][3])
                    : "r"(ad));
            }
            // B: one x4.trans per 2 n-tiles.  lane group g = lane>>3:
            //   matrices 0,1 -> (k0-7, k8-15) of tile ni ; 2,3 -> of tile ni+1
#pragma unroll
            for (int ni = 0; ni < 4; ni += 2) {
                const int g  = lane >> 3;
                const int kl = k16 * 16 + (g & 1) * 8 + (lane & 7);
                const int gn = wn * 4 + ni + (g >> 1);
                const uint32_t bd = bB + BSWZ(kl, gn);
                asm volatile("ldmatrix.sync.aligned.m8n8.x4.trans.shared.b16 {%0,%1,%2,%3}, [%4];"
                    : "=r"(bf[ni][0]), "=r"(bf[ni][1]),
                      "=r"(bf[ni + 1][0]), "=r"(bf[ni + 1][1])
                    : "r"(bd));
            }
#pragma unroll
            for (int mi = 0; mi < 4; mi++)
#pragma unroll
                for (int ni = 0; ni < 4; ni++)
                    asm volatile(
                        "mma.sync.aligned.m16n8k16.row.col.f32.f16.f16.f32 "
                        "{%0,%1,%2,%3}, {%4,%5,%6,%7}, {%8,%9}, {%0,%1,%2,%3};"
                        : "+f"(acc[mi][ni][0]), "+f"(acc[mi][ni][1]),
                          "+f"(acc[mi][ni][2]), "+f"(acc[mi][ni][3])
                        : "r"(af[mi][0]), "r"(af[mi][1]), "r"(af[mi][2]), "r"(af[mi][3]),
                          "r"(bf[ni][0]), "r"(bf[ni][1]));
        }
        __syncthreads();
    }
#undef LOAD_STAGE

    // epilogue: fp16 stores (c0,c1)=(row, col..col+1), (c2,c3)=row+8
#pragma unroll
    for (int mi = 0; mi < 4; mi++) {
        const int r0 = m0 + wm * 64 + mi * 16 + (lane >> 2);
#pragma unroll
        for (int ni = 0; ni < 4; ni++) {
            const int c = n0 + wn * 32 + ni * 8 + (lane & 3) * 2;
            if (r0 < NNODES)
                *reinterpret_cast<__half2*>(C + r0 * LAT + c) =
                    __floats2half2_rn(acc[mi][ni][0], acc[mi][ni][1]);
            if (r0 + 8 < NNODES)
                *reinterpret_cast<__half2*>(C + (r0 + 8) * LAT + c) =
                    __floats2half2_rn(acc[mi][ni][2], acc[mi][ni][3]);
        }
    }
}

// ============================================================================
// prep: fp16 conversion of the 6 weight matrices (layout kept [k][n])
// ============================================================================
__global__ __launch_bounds__(256)
void prep_w(const float* __restrict__ Ws, const float* __restrict__ Wn)
{
    const int idx = blockIdx.x * 256 + threadIdx.x;     // < 6*65536
    const int p = idx >> 16, rem = idx & 65535;
    const float* src = (p & 1) ? Wn : Ws;
    g_Whf[idx] = __float2half(src[(p >> 1) * 65536 + rem]);
}

// convert fp32 x -> fp16 hi/lo (step-0 input)
__global__ __launch_bounds__(256)
void cvt_x(const float* __restrict__ x)
{
    const int i = (blockIdx.x * 256 + threadIdx.x) * 4;
    const float4 v = *reinterpret_cast<const float4*>(x + i);
    __half h0 = __float2half(v.x), h1 = __float2half(v.y);
    __half h2 = __float2half(v.z), h3 = __float2half(v.w);
    __half l0 = __float2half(v.x - __half2float(h0));
    __half l1 = __float2half(v.y - __half2float(h1));
    __half l2 = __float2half(v.z - __half2float(h2));
    __half l3 = __float2half(v.w - __half2float(h3));
    *reinterpret_cast<__half2*>(g_xhi + i)     = __halves2half2(h0, h1);
    *reinterpret_cast<__half2*>(g_xhi + i + 2) = __halves2half2(h2, h3);
    *reinterpret_cast<__half2*>(g_xlo + i)     = __halves2half2(l0, l1);
    *reinterpret_cast<__half2*>(g_xlo + i + 2) = __halves2half2(l2, l3);
}

// ============================================================================
// combine: h = x + S + bs + bn + (1/6)*sum Nn[nbr]; y = relu(LN(h)*g+b)
//   x comes from x32 (fp32) if non-null, else reconstructed as xhi+xlo.
//   S / Nn read as fp16.  Writes fp32 out and/or fp16 hi/lo pair.
// 128 threads = 2 rows per block; each 64-thread half owns one row.
// ============================================================================
__global__ __launch_bounds__(128)
void combine_k(const float* __restrict__ x32,
               const __half* __restrict__ xhin,
               const __half* __restrict__ xlin,
               const float* __restrict__ bsv,
               const float* __restrict__ bnv,
               const float* __restrict__ gam,
               const float* __restrict__ bet,
               const int*   __restrict__ nbr,
               float*       __restrict__ out,
               __half* __restrict__ oxh,
               __half* __restrict__ oxl)
{
    const int half_ = threadIdx.x >> 6;            // 0 or 1
    const int row  = blockIdx.x * 2 + half_;
    const int t    = threadIdx.x & 63;
    const int j    = t << 2;
    const int base = row * LAT + j;

    const int* nb = nbr + row * KNB;
    const int n0 = nb[0], n1 = nb[1], n2 = nb[2], n3 = nb[3], n4 = nb[4], n5 = nb[5];

    float4 xv;
    if (x32) {
        xv = *reinterpret_cast<const float4*>(x32 + base);
    } else {
        const __half2 h0 = *reinterpret_cast<const __half2*>(xhin + base);
        const __half2 h1 = *reinterpret_cast<const __half2*>(xhin + base + 2);
        const __half2 l0 = *reinterpret_cast<const __half2*>(xlin + base);
        const __half2 l1 = *reinterpret_cast<const __half2*>(xlin + base + 2);
        xv.x = __half2float(h0.x) + __half2float(l0.x);
        xv.y = __half2float(h0.y) + __half2float(l0.y);
        xv.z = __half2float(h1.x) + __half2float(l1.x);
        xv.w = __half2float(h1.y) + __half2float(l1.y);
    }

    // S (fp16 -> fp32)
    float4 sv;
    {
        const __half2 s0 = *reinterpret_cast<const __half2*>(g_S + base);
        const __half2 s1 = *reinterpret_cast<const __half2*>(g_S + base + 2);
        const float2 f0 = __half22float2(s0), f1 = __half22float2(s1);
        sv = make_float4(f0.x, f0.y, f1.x, f1.y);
    }

    // Nn gather (fp16 -> fp32 accumulate over 6 neighbors)
    float4 a = make_float4(0.f, 0.f, 0.f, 0.f);
    const int nn[6] = {n0, n1, n2, n3, n4, n5};
#pragma unroll
    for (int q = 0; q < 6; q++) {
        const __half2 g0 = *reinterpret_cast<const __half2*>(g_Nn + nn[q] * LAT + j);
        const __half2 g1 = *reinterpret_cast<const __half2*>(g_Nn + nn[q] * LAT + j + 2);
        const float2 f0 = __half22float2(g0), f1 = __half22float2(g1);
        a.x += f0.x; a.y += f0.y; a.z += f1.x; a.w += f1.y;
    }

    const float4 bq = *reinterpret_cast<const float4*>(bsv + j);
    const float4 nq = *reinterpret_cast<const float4*>(bnv + j);

    const float inv6 = 1.0f / 6.0f;
    float4 h;
    h.x = xv.x + sv.x + bq.x + nq.x + a.x * inv6;
    h.y = xv.y + sv.y + bq.y + nq.y + a.y * inv6;
    h.z = xv.z + sv.z + bq.z + nq.z + a.z * inv6;
    h.w = xv.w + sv.w + bq.w + nq.w + a.w * inv6;

    float s = h.x + h.y + h.z + h.w;
    float q = fmaf(h.x, h.x, fmaf(h.y, h.y, fmaf(h.z, h.z, h.w * h.w)));
#pragma unroll
    for (int o = 16; o > 0; o >>= 1) {
        s += __shfl_xor_sync(0xffffffffu, s, o);
        q += __shfl_xor_sync(0xffffffffu, q, o);
    }
    __shared__ float sh[2][4];
    if ((t & 31) == 0) { sh[half_][(t >> 5) * 2] = s; sh[half_][(t >> 5) * 2 + 1] = q; }
    __syncthreads();
    s = sh[half_][0] + sh[half_][2];
    q = sh[half_][1] + sh[half_][3];

    const float mu  = s * (1.0f / LAT);
    const float var = q * (1.0f / LAT) - mu * mu;
    const float inv = rsqrtf(var + LN_EPS);

    const float4 g = *reinterpret_cast<const float4*>(gam + j);
    const float4 b = *reinterpret_cast<const float4*>(bet + j);

    float4 o4;
    o4.x = fmaxf(0.0f, (h.x - mu) * inv * g.x + b.x);
    o4.y = fmaxf(0.0f, (h.y - mu) * inv * g.y + b.y);
    o4.z = fmaxf(0.0f, (h.z - mu) * inv * g.z + b.z);
    o4.w = fmaxf(0.0f, (h.w - mu) * inv * g.w + b.w);

    if (out)
        *reinterpret_cast<float4*>(out + base) = o4;

    if (oxh) {
        __half h0 = __float2half(o4.x), h1 = __float2half(o4.y);
        __half h2 = __float2half(o4.z), h3 = __float2half(o4.w);
        __half l0 = __float2half(o4.x - __half2float(h0));
        __half l1 = __float2half(o4.y - __half2float(h1));
        __half l2 = __float2half(o4.z - __half2float(h2));
        __half l3 = __float2half(o4.w - __half2float(h3));
        *reinterpret_cast<__half2*>(oxh + base)     = __halves2half2(h0, h1);
        *reinterpret_cast<__half2*>(oxh + base + 2) = __halves2half2(h2, h3);
        *reinterpret_cast<__half2*>(oxl + base)     = __halves2half2(l0, l1);
        *reinterpret_cast<__half2*>(oxl + base + 2) = __halves2half2(l2, l3);
    }
}

extern "C" void kernel_launch(void* const* d_in, const int* in_sizes, int n_in,
                              void* d_out, int out_size)
{
    const float* x0  = (const float*)d_in[0];
    const float* Ws  = (const float*)d_in[1];
    const float* bs  = (const float*)d_in[2];
    const float* Wn  = (const float*)d_in[3];
    const float* bn  = (const float*)d_in[4];
    const float* lsc = (const float*)d_in[5];
    const float* lof = (const float*)d_in[6];
    const int*   nbr = (const int*)d_in[7];
    float* out = (float*)d_out;

    __half *xhi = nullptr, *xlo = nullptr;
    cudaGetSymbolAddress((void**)&xhi, g_xhi);
    cudaGetSymbolAddress((void**)&xlo, g_xlo);

    cudaFuncSetAttribute(gemm_mma, cudaFuncAttributeMaxDynamicSharedMemorySize, GEMM_SMEM);

    const dim3 gg(LAT / BN, NTILES, 2);   // (2, 391, 2)
    const dim3 gb(256);
    const dim3 cg(NNODES / 2);            // 25000 blocks x 2 rows
    const dim3 cb(128);

    prep_w<<<6 * 65536 / 256, 256>>>(Ws, Wn);
    cvt_x<<<NNODES * LAT / 1024, 256>>>(x0);

    // step 0: residual from fp32 input; emit hi/lo only
    gemm_mma<<<gg, gb, GEMM_SMEM>>>(xhi, 0);
    combine_k<<<cg, cb>>>(x0, xhi, xlo, bs, bn, lsc, lof, nbr,
                          (float*)nullptr, xhi, xlo);
    // step 1: residual from hi+lo; emit hi/lo only
    gemm_mma<<<gg, gb, GEMM_SMEM>>>(xhi, 2);
    combine_k<<<cg, cb>>>((const float*)nullptr, xhi, xlo,
                          bs + LAT, bn + LAT, lsc + LAT, lof + LAT, nbr,
                          (float*)nullptr, xhi, xlo);
    // step 2: residual from hi+lo; emit fp32 d_out only
    gemm_mma<<<gg, gb, GEMM_SMEM>>>(xhi, 4);
    combine_k<<<cg, cb>>>((const float*)nullptr, xhi, xlo,
                          bs + 2 * LAT, bn + 2 * LAT, lsc + 2 * LAT, lof + 2 * LAT, nbr,
                          out, (__half*)nullptr, (__half*)nullptr);
}